// round 5
// baseline (speedup 1.0000x reference)
#include <cuda_runtime.h>

// ---------------- problem constants (raster grid 1024x1024) ----------------
#define R_  1024
#define C_  1024
#define N_  (R_ * C_)
#define HL_ (R_ * (C_ - 1))          // horizontal link count
#define L_  (HL_ + (R_ - 1) * C_)    // total links = 2,095,104
#define ITERS_ 15
#define NSLOT 32
#define F4ROW (C_ / 4)               // 256 float4 per row
#define TOT4  (N_ / 4)               // 262144 float4 total

// persistent-kernel shape: 256 blocks x 256 threads, all co-resident
#define NBLK 256
#define NTHR 256
#define NT   (NBLK * NTHR)           // 65536 threads
#define ITEMS (TOT4 / NT)            // 4 float4 items per thread per phase

#define K_FLOW_  0.0405f
#define FLOW_EXP_ 1.25f
#define A_OPEN_  1.3455e-09f
#define C_CLOSE_ 7.11e-24f
#define RWG_     9810.0f             // rho_w * g
#define INV_DX_  (1.0f / 100.0f)
#define INV_DX2_ (1.0f / (100.0f * 100.0f))

// ---------------- device scratch (static; no allocations) ----------------
__device__ __align__(16) float g_x [N_];
__device__ __align__(16) float g_r [N_];
__device__ __align__(16) float g_p [N_];
__device__ __align__(16) float g_v [N_];
__device__ __align__(16) float g_s [N_];
__device__ __align__(16) float g_t [N_];
__device__ __align__(16) float g_r0[N_];
__device__ __align__(16) float g_grad[L_];

// BiCGSTAB scalar state: 32 contention-spread slots per logical scalar.
__device__ double g_rho [(ITERS_ + 2) * NSLOT];
__device__ double g_dr0v[(ITERS_ + 1) * NSLOT];
__device__ double g_dts [(ITERS_ + 1) * NSLOT];
__device__ double g_dtt [(ITERS_ + 1) * NSLOT];

// grid-barrier counters, one per phase; zeroed by k_grad every replay
#define NPHASE 64
__device__ volatile unsigned g_bar[NPHASE];

#define EPSD 1e-30

__device__ __forceinline__ double slotsum(const double* p) {
    double a = 0.0;
    #pragma unroll
    for (int i = 0; i < NSLOT; i++) a += p[i];
    return a;
}

// ---------------- grid barrier (256 co-resident blocks) ----------------
__device__ __forceinline__ void gbar(int ph) {
    __syncthreads();
    if (threadIdx.x == 0) {
        __threadfence();
        atomicAdd((unsigned*)(g_bar + ph), 1u);
        while (g_bar[ph] != (unsigned)NBLK) { }
        __threadfence();
    }
    __syncthreads();
}

// ---------------- reduction helpers (256-thread blocks) ----------------
__device__ __forceinline__ void block_red1(double v, double* dst) {
    #pragma unroll
    for (int o = 16; o > 0; o >>= 1) v += __shfl_down_sync(0xffffffffu, v, o);
    __shared__ double sm1[8];
    int lane = threadIdx.x & 31, w = threadIdx.x >> 5;
    if (lane == 0) sm1[w] = v;
    __syncthreads();
    if (threadIdx.x < 8) {
        v = sm1[threadIdx.x];
        #pragma unroll
        for (int o = 4; o > 0; o >>= 1) v += __shfl_down_sync(0xffu, v, o);
        if (threadIdx.x == 0) atomicAdd(dst, v);
    }
    __syncthreads();
}

__device__ __forceinline__ void block_red2(double a, double b, double* da, double* db) {
    #pragma unroll
    for (int o = 16; o > 0; o >>= 1) {
        a += __shfl_down_sync(0xffffffffu, a, o);
        b += __shfl_down_sync(0xffffffffu, b, o);
    }
    __shared__ double sma[8], smb[8];
    int lane = threadIdx.x & 31, w = threadIdx.x >> 5;
    if (lane == 0) { sma[w] = a; smb[w] = b; }
    __syncthreads();
    if (threadIdx.x < 8) {
        a = sma[threadIdx.x];
        b = smb[threadIdx.x];
        #pragma unroll
        for (int o = 4; o > 0; o >>= 1) {
            a += __shfl_down_sync(0xffu, a, o);
            b += __shfl_down_sync(0xffu, b, o);
        }
        if (threadIdx.x == 0) { atomicAdd(da, a); atomicAdd(db, b); }
    }
    __syncthreads();
}

// ---------------- stencil helpers ----------------
__device__ __forceinline__ float xbv(const float* __restrict__ x,
                                     const int* __restrict__ io,
                                     const float* __restrict__ bed,
                                     int r, int c) {
    int n = r * C_ + c;
    float xv = __ldg(&x[n]);
    if (r == 0 || r == R_ - 1 || c == 0 || c == C_ - 1) {
        if (__ldg(&io[n]) == -1) xv = RWG_ * __ldg(&bed[n]);
    }
    return xv;
}

__device__ __forceinline__ float matvec_at(const float* __restrict__ x,
                                           const int* __restrict__ io,
                                           const float* __restrict__ bed,
                                           int r, int c) {
    float xc = xbv(x, io, bed, r, c);
    float a = 0.f;
    if (c > 0)      a += xbv(x, io, bed, r, c - 1) - xc;
    if (c < C_ - 1) a += xbv(x, io, bed, r, c + 1) - xc;
    if (r > 0)      a += xbv(x, io, bed, r - 1, c) - xc;
    if (r < R_ - 1) a += xbv(x, io, bed, r + 1, c) - xc;
    return a * INV_DX2_;
}

// interior 5-point stencil, same add order: left, right, up, down
__device__ __forceinline__ float sten(float l, float rt, float u, float d, float c) {
    float a = (l - c);
    a += (rt - c);
    a += (u - c);
    a += (d - c);
    return a * INV_DX2_;
}

__device__ __forceinline__ float4 sten4(float4 xc, float4 xu, float4 xd, float xl, float xr) {
    float4 o;
    o.x = sten(xl,   xc.y, xu.x, xd.x, xc.x);
    o.y = sten(xc.x, xc.z, xu.y, xd.y, xc.y);
    o.z = sten(xc.y, xc.w, xu.z, xd.z, xc.z);
    o.w = sten(xc.z, xr,   xu.w, xd.w, xc.w);
    return o;
}

__device__ __forceinline__ double dot4(float4 a, float4 b) {
    return (double)(a.x * b.x) + (double)(a.y * b.y)
         + (double)(a.z * b.z) + (double)(a.w * b.w);
}

// s = r - alpha*v helpers (used by matvec_t edge path; identical to prior rounds)
__device__ __forceinline__ float4 s4(float4 rv, float4 vv, float al) {
    float4 o;
    o.x = rv.x - al * vv.x;
    o.y = rv.y - al * vv.y;
    o.z = rv.z - al * vv.z;
    o.w = rv.w - al * vv.w;
    return o;
}
__device__ __forceinline__ float s1(int n, float al) {
    return __ldg(&g_r[n]) - al * __ldg(&g_v[n]);
}
__device__ __forceinline__ float sb1(const int* __restrict__ io,
                                     const float* __restrict__ bed,
                                     int r, int c, float al) {
    int n = r * C_ + c;
    float sv = s1(n, al);
    if (r == 0 || r == R_ - 1 || c == 0 || c == C_ - 1) {
        if (__ldg(&io[n]) == -1) sv = RWG_ * __ldg(&bed[n]);
    }
    return sv;
}
__device__ __forceinline__ float t_at(const int* __restrict__ io,
                                      const float* __restrict__ bed,
                                      int r, int c, float al) {
    float xc = sb1(io, bed, r, c, al);
    float a = 0.f;
    if (c > 0)      a += sb1(io, bed, r, c - 1, al) - xc;
    if (c < C_ - 1) a += sb1(io, bed, r, c + 1, al) - xc;
    if (r > 0)      a += sb1(io, bed, r - 1, c, al) - xc;
    if (r < R_ - 1) a += sb1(io, bed, r + 1, c, al) - xc;
    return a * INV_DX2_;
}

// ---------------- init helpers ----------------
__device__ __forceinline__ float xb0v(const int* __restrict__ io,
                                      const float* __restrict__ bed, int r, int c) {
    if (r == 0 || r == R_ - 1 || c == 0 || c == C_ - 1) {
        int n = r * C_ + c;
        if (__ldg(&io[n]) == -1) return RWG_ * __ldg(&bed[n]);
    }
    return 0.f;
}

__device__ __forceinline__ float init_r0_at(const int* __restrict__ io,
                                            const float* __restrict__ bed,
                                            int r, int c) {
    int n = r * C_ + c;
    float acc = 0.f;
    if (c < C_ - 1) acc += g_grad[r * (C_ - 1) + c];
    if (r < R_ - 1) acc += g_grad[HL_ + n];
    if (c > 0)      acc -= g_grad[r * (C_ - 1) + c - 1];
    if (r > 0)      acc -= g_grad[HL_ + n - C_];
    float b = acc * INV_DX_;
    float xc = xb0v(io, bed, r, c);
    float a = 0.f;
    if (c > 0)      a += xb0v(io, bed, r, c - 1) - xc;
    if (c < C_ - 1) a += xb0v(io, bed, r, c + 1) - xc;
    if (r > 0)      a += xb0v(io, bed, r - 1, c) - xc;
    if (r < R_ - 1) a += xb0v(io, bed, r + 1, c) - xc;
    return b - a * INV_DX2_;
}

// ---------------- prologue kernel: grad + zero slots + zero barriers --------
__global__ void __launch_bounds__(256) k_grad(const float* __restrict__ cs,
                                              const float* __restrict__ q,
                                              const int* __restrict__ fd) {
    int l = blockIdx.x * blockDim.x + threadIdx.x;
    if (blockIdx.x == 0) {
        for (int i = threadIdx.x; i < (ITERS_ + 2) * NSLOT; i += 256)
            g_rho[i] = (i == 0) ? 1.0 : 0.0;
        for (int i = threadIdx.x; i < (ITERS_ + 1) * NSLOT; i += 256) {
            double v = (i == 0) ? 1.0 : 0.0;
            g_dr0v[i] = v; g_dts[i] = v; g_dtt[i] = v;
        }
        for (int i = threadIdx.x; i < NPHASE; i += 256)
            ((unsigned*)g_bar)[i] = 0u;
    }
    if (l < L_) {
        float s = cs[l];
        float g = q[l] / (K_FLOW_ * powf(s, FLOW_EXP_));
        g_grad[l] = g * g * (float)fd[l];
    }
}

// ---------------- the persistent solver kernel ----------------
__global__ void __launch_bounds__(NTHR, 2) k_solve(const int* __restrict__ io,
                                                   const float* __restrict__ bed) {
    __shared__ float shs[2];
    const int gid  = blockIdx.x * NTHR + threadIdx.x;
    const int slot = blockIdx.x & (NSLOT - 1);
    int ph = 0;

    // ---- phase: init r0 = b - A(0), zero x/p/v, rho[1] = dot(r0,r0) ----
    {
        double acc = 0.0;
        #pragma unroll
        for (int k = 0; k < ITEMS; k++) {
            int i4 = gid + k * NT;
            int n = i4 << 2, rr = n >> 10, c0 = n & (C_ - 1);
            float4 r0v;
            r0v.x = init_r0_at(io, bed, rr, c0 + 0);
            r0v.y = init_r0_at(io, bed, rr, c0 + 1);
            r0v.z = init_r0_at(io, bed, rr, c0 + 2);
            r0v.w = init_r0_at(io, bed, rr, c0 + 3);
            ((float4*)g_r0)[i4] = r0v;
            ((float4*)g_r )[i4] = r0v;
            float4 z = make_float4(0.f, 0.f, 0.f, 0.f);
            ((float4*)g_x)[i4] = z;
            ((float4*)g_p)[i4] = z;
            ((float4*)g_v)[i4] = z;
            acc += dot4(r0v, r0v);
        }
        block_red1(acc, &g_rho[1 * NSLOT + slot]);
        gbar(ph++);
    }

    for (int it = 0; it < ITERS_; ++it) {
        // ---- phase 1: p = r + beta*(p - omega_prev*v) ----
        if (threadIdx.x == 0) {
            double rho_n   = slotsum(&g_rho [(it + 1) * NSLOT]);
            double rho_p   = slotsum(&g_rho [ it      * NSLOT]);
            double alpha_p = rho_p / (slotsum(&g_dr0v[it * NSLOT]) + EPSD);
            double omega_p = slotsum(&g_dts[it * NSLOT]) /
                             (slotsum(&g_dtt[it * NSLOT]) + EPSD);
            shs[0] = (float)((rho_n / (rho_p + EPSD)) * (alpha_p / (omega_p + EPSD)));
            shs[1] = (float)omega_p;
        }
        __syncthreads();
        {
            float beta = shs[0], om = shs[1];
            #pragma unroll
            for (int k = 0; k < ITEMS; k++) {
                int i4 = gid + k * NT;
                float4 rv = ((const float4*)g_r)[i4];
                float4 pv = ((const float4*)g_p)[i4];
                float4 vv = ((const float4*)g_v)[i4];
                float4 o;
                o.x = rv.x + beta * (pv.x - om * vv.x);
                o.y = rv.y + beta * (pv.y - om * vv.y);
                o.z = rv.z + beta * (pv.z - om * vv.z);
                o.w = rv.w + beta * (pv.w - om * vv.w);
                ((float4*)g_p)[i4] = o;
            }
        }
        gbar(ph++);

        // ---- phase 2: v = A(p), dot(r0,v) ----
        {
            double acc = 0.0;
            #pragma unroll 2
            for (int k = 0; k < ITEMS; k++) {
                int i4 = gid + k * NT;
                int n = i4 << 2, rr = n >> 10, c0 = n & (C_ - 1);
                float4 vout;
                if (rr >= 2 && rr <= R_ - 3 && c0 >= 4 && c0 <= C_ - 8) {
                    float4 xc = ((const float4*)g_p)[i4];
                    float4 xu = ((const float4*)g_p)[i4 - F4ROW];
                    float4 xd = ((const float4*)g_p)[i4 + F4ROW];
                    float xl = __ldg(&g_p[n - 1]);
                    float xr = __ldg(&g_p[n + 4]);
                    vout = sten4(xc, xu, xd, xl, xr);
                } else {
                    vout.x = matvec_at(g_p, io, bed, rr, c0 + 0);
                    vout.y = matvec_at(g_p, io, bed, rr, c0 + 1);
                    vout.z = matvec_at(g_p, io, bed, rr, c0 + 2);
                    vout.w = matvec_at(g_p, io, bed, rr, c0 + 3);
                }
                ((float4*)g_v)[i4] = vout;
                acc += dot4(((const float4*)g_r0)[i4], vout);
            }
            block_red1(acc, &g_dr0v[(it + 1) * NSLOT + slot]);
        }
        gbar(ph++);

        // ---- phase 3: s = r - al*v ; t = A(s) ; dot(t,s), dot(t,t) ----
        if (threadIdx.x == 0) {
            double rho_n = slotsum(&g_rho[(it + 1) * NSLOT]);
            shs[0] = (float)(rho_n / (slotsum(&g_dr0v[(it + 1) * NSLOT]) + EPSD));
        }
        __syncthreads();
        {
            float al = shs[0];
            double ats = 0.0, att = 0.0;
            #pragma unroll 2
            for (int k = 0; k < ITEMS; k++) {
                int i4 = gid + k * NT;
                int n = i4 << 2, rr = n >> 10, c0 = n & (C_ - 1);
                float4 t0, sc;
                if (rr >= 2 && rr <= R_ - 3 && c0 >= 4 && c0 <= C_ - 8) {
                    float4 sm_ = s4(((const float4*)g_r)[i4 - F4ROW],
                                    ((const float4*)g_v)[i4 - F4ROW], al);
                    sc         = s4(((const float4*)g_r)[i4],
                                    ((const float4*)g_v)[i4], al);
                    float4 sd  = s4(((const float4*)g_r)[i4 + F4ROW],
                                    ((const float4*)g_v)[i4 + F4ROW], al);
                    float sl = s1(n - 1, al);
                    float sr = s1(n + 4, al);
                    t0 = sten4(sc, sm_, sd, sl, sr);
                } else {
                    sc.x = s1(n + 0, al); sc.y = s1(n + 1, al);
                    sc.z = s1(n + 2, al); sc.w = s1(n + 3, al);
                    t0.x = t_at(io, bed, rr, c0 + 0, al);
                    t0.y = t_at(io, bed, rr, c0 + 1, al);
                    t0.z = t_at(io, bed, rr, c0 + 2, al);
                    t0.w = t_at(io, bed, rr, c0 + 3, al);
                }
                ((float4*)g_s)[i4] = sc;
                ((float4*)g_t)[i4] = t0;
                ats += dot4(t0, sc);
                att += dot4(t0, t0);
            }
            block_red2(ats, att,
                       &g_dts[(it + 1) * NSLOT + slot],
                       &g_dtt[(it + 1) * NSLOT + slot]);
        }
        gbar(ph++);

        // ---- phase 4: x += al*p + om*s ; r = s - om*t ; dot(r0, r_new) ----
        if (threadIdx.x == 0) {
            double rho_n = slotsum(&g_rho[(it + 1) * NSLOT]);
            shs[0] = (float)(rho_n / (slotsum(&g_dr0v[(it + 1) * NSLOT]) + EPSD));
            shs[1] = (float)(slotsum(&g_dts[(it + 1) * NSLOT]) /
                             (slotsum(&g_dtt[(it + 1) * NSLOT]) + EPSD));
        }
        __syncthreads();
        {
            float al = shs[0], om = shs[1];
            double d = 0.0;
            #pragma unroll
            for (int k = 0; k < ITEMS; k++) {
                int i4 = gid + k * NT;
                float4 xv  = ((const float4*)g_x )[i4];
                float4 pv  = ((const float4*)g_p )[i4];
                float4 sv  = ((const float4*)g_s )[i4];
                float4 tv  = ((const float4*)g_t )[i4];
                float4 r0v = ((const float4*)g_r0)[i4];
                float4 xn, rn;
                xn.x = (xv.x + al * pv.x) + om * sv.x;  rn.x = sv.x - om * tv.x;
                xn.y = (xv.y + al * pv.y) + om * sv.y;  rn.y = sv.y - om * tv.y;
                xn.z = (xv.z + al * pv.z) + om * sv.z;  rn.z = sv.z - om * tv.z;
                xn.w = (xv.w + al * pv.w) + om * sv.w;  rn.w = sv.w - om * tv.w;
                ((float4*)g_x)[i4] = xn;
                ((float4*)g_r)[i4] = rn;
                d += dot4(r0v, rn);
            }
            block_red1(d, &g_rho[(it + 2) * NSLOT + slot]);
        }
        gbar(ph++);
    }
}

// ---------------- epilogue ----------------
__device__ __forceinline__ float eff_at(const float* __restrict__ bed,
                                        const float* __restrict__ ob, int n) {
    float pd = g_x[n] - RWG_ * __ldg(&bed[n]);
    float o  = __ldg(&ob[n]);
    float wp = fminf(fmaxf(pd, 0.f), o);
    return o - wp;
}

__global__ void __launch_bounds__(256) k_out(const float* __restrict__ cs,
                                             const float* __restrict__ q,
                                             const int* __restrict__ fd,
                                             const int* __restrict__ head,
                                             const int* __restrict__ tail,
                                             float* __restrict__ out,
                                             const int* __restrict__ dtp,
                                             const float* __restrict__ bed,
                                             const float* __restrict__ ob) {
    int l = blockIdx.x * blockDim.x + threadIdx.x;
    if (l >= L_) return;
    float dtf = (float)__ldg(dtp);
    int h = __ldg(&head[l]), t = __ldg(&tail[l]);
    float el = fmaxf(0.5f * (eff_at(bed, ob, h) + eff_at(bed, ob, t)), 1.0f);
    float s = cs[l];
    float melt = A_OPEN_ * q[l] * g_grad[l] * (float)fd[l];
    float closure = C_CLOSE_ * (el * el * el) * s;
    out[l] = fmaxf(s + (melt - closure) * dtf, 0.001f);
}

// ---------------- launch ----------------
extern "C" void kernel_launch(void* const* d_in, const int* in_sizes, int n_in,
                              void* d_out, int out_size) {
    const float* cs   = (const float*)d_in[0];
    const float* q    = (const float*)d_in[1];
    const float* bed  = (const float*)d_in[2];
    const float* ob   = (const float*)d_in[3];
    const int*   fd   = (const int*)  d_in[4];
    const int*   io   = (const int*)  d_in[5];
    const int*   head = (const int*)  d_in[6];
    const int*   tail = (const int*)  d_in[7];
    const int*   dtp  = (const int*)  d_in[8];
    float* out = (float*)d_out;

    const int TB = 256;
    const int GB_L = (L_ + TB - 1) / TB;   // 8184

    k_grad<<<GB_L, TB>>>(cs, q, fd);
    k_solve<<<NBLK, NTHR>>>(io, bed);
    k_out<<<GB_L, TB>>>(cs, q, fd, head, tail, out, dtp, bed, ob);
}

// round 6
// speedup vs baseline: 1.0826x; 1.0826x over previous
#include <cuda_runtime.h>

// ---------------- problem constants (raster grid 1024x1024) ----------------
#define R_  1024
#define C_  1024
#define N_  (R_ * C_)
#define HL_ (R_ * (C_ - 1))          // horizontal link count
#define L_  (HL_ + (R_ - 1) * C_)    // total links = 2,095,104
#define ITERS_ 15
#define NSLOT 32
#define F4ROW (C_ / 4)               // 256 float4 per row
#define TOT4  (N_ / 4)               // 262144 float4 total
#define NTHR  256

#define K_FLOW_  0.0405f
#define FLOW_EXP_ 1.25f
#define A_OPEN_  1.3455e-09f
#define C_CLOSE_ 7.11e-24f
#define RWG_     9810.0f             // rho_w * g
#define INV_DX_  (1.0f / 100.0f)
#define INV_DX2_ (1.0f / (100.0f * 100.0f))

// ---------------- device scratch (static; no allocations) ----------------
__device__ __align__(16) float g_x [N_];
__device__ __align__(16) float g_r [N_];
__device__ __align__(16) float g_p [N_];
__device__ __align__(16) float g_v [N_];
__device__ __align__(16) float g_s [N_];
__device__ __align__(16) float g_t [N_];
__device__ __align__(16) float g_r0[N_];
__device__ __align__(16) float g_grad[L_];

// BiCGSTAB scalar state: 32 contention-spread slots per logical scalar.
__device__ double g_rho [(ITERS_ + 2) * NSLOT];
__device__ double g_dr0v[(ITERS_ + 1) * NSLOT];
__device__ double g_dts [(ITERS_ + 1) * NSLOT];
__device__ double g_dtt [(ITERS_ + 1) * NSLOT];

// grid-barrier counters, one per phase; zeroed by k_grad every replay
#define NPHASE 64
__device__ volatile unsigned g_bar[NPHASE];

#define EPSD 1e-30

__device__ __forceinline__ double slotsum(const double* p) {
    double a = 0.0;
    #pragma unroll
    for (int i = 0; i < NSLOT; i++) a += p[i];
    return a;
}

// ---------------- grid barrier (all blocks co-resident by construction) ----
__device__ __forceinline__ void gbar(int ph) {
    __syncthreads();
    if (threadIdx.x == 0) {
        unsigned target = gridDim.x;
        __threadfence();
        atomicAdd((unsigned*)(g_bar + ph), 1u);
        while (g_bar[ph] != target) { }
        __threadfence();
    }
    __syncthreads();
}

// ---------------- reductions: f32 to warp level, f64 above ----------------
__device__ __forceinline__ void red1f(float v, double* dst) {
    #pragma unroll
    for (int o = 16; o > 0; o >>= 1) v += __shfl_down_sync(0xffffffffu, v, o);
    __shared__ double sm1[8];
    int lane = threadIdx.x & 31, w = threadIdx.x >> 5;
    if (lane == 0) sm1[w] = (double)v;
    __syncthreads();
    if (threadIdx.x < 8) {
        double d = sm1[threadIdx.x];
        #pragma unroll
        for (int o = 4; o > 0; o >>= 1) d += __shfl_down_sync(0xffu, d, o);
        if (threadIdx.x == 0) atomicAdd(dst, d);
    }
    __syncthreads();
}

__device__ __forceinline__ void red2f(float a, float b, double* da, double* db) {
    #pragma unroll
    for (int o = 16; o > 0; o >>= 1) {
        a += __shfl_down_sync(0xffffffffu, a, o);
        b += __shfl_down_sync(0xffffffffu, b, o);
    }
    __shared__ double sma[8], smb[8];
    int lane = threadIdx.x & 31, w = threadIdx.x >> 5;
    if (lane == 0) { sma[w] = (double)a; smb[w] = (double)b; }
    __syncthreads();
    if (threadIdx.x < 8) {
        double da_ = sma[threadIdx.x];
        double db_ = smb[threadIdx.x];
        #pragma unroll
        for (int o = 4; o > 0; o >>= 1) {
            da_ += __shfl_down_sync(0xffu, da_, o);
            db_ += __shfl_down_sync(0xffu, db_, o);
        }
        if (threadIdx.x == 0) { atomicAdd(da, da_); atomicAdd(db, db_); }
    }
    __syncthreads();
}

__device__ __forceinline__ float dot4f(float4 a, float4 b) {
    return a.x * b.x + a.y * b.y + a.z * b.z + a.w * b.w;
}

// ---------------- stencil helpers (per-element f32 expressions UNCHANGED) ----
__device__ __forceinline__ float xbv(const float* __restrict__ x,
                                     const int* __restrict__ io,
                                     const float* __restrict__ bed,
                                     int r, int c) {
    int n = r * C_ + c;
    float xv = __ldg(&x[n]);
    if (r == 0 || r == R_ - 1 || c == 0 || c == C_ - 1) {
        if (__ldg(&io[n]) == -1) xv = RWG_ * __ldg(&bed[n]);
    }
    return xv;
}

__device__ __forceinline__ float matvec_at(const float* __restrict__ x,
                                           const int* __restrict__ io,
                                           const float* __restrict__ bed,
                                           int r, int c) {
    float xc = xbv(x, io, bed, r, c);
    float a = 0.f;
    if (c > 0)      a += xbv(x, io, bed, r, c - 1) - xc;
    if (c < C_ - 1) a += xbv(x, io, bed, r, c + 1) - xc;
    if (r > 0)      a += xbv(x, io, bed, r - 1, c) - xc;
    if (r < R_ - 1) a += xbv(x, io, bed, r + 1, c) - xc;
    return a * INV_DX2_;
}

__device__ __forceinline__ float sten(float l, float rt, float u, float d, float c) {
    float a = (l - c);
    a += (rt - c);
    a += (u - c);
    a += (d - c);
    return a * INV_DX2_;
}

__device__ __forceinline__ float4 sten4(float4 xc, float4 xu, float4 xd, float xl, float xr) {
    float4 o;
    o.x = sten(xl,   xc.y, xu.x, xd.x, xc.x);
    o.y = sten(xc.x, xc.z, xu.y, xd.y, xc.y);
    o.z = sten(xc.y, xc.w, xu.z, xd.z, xc.z);
    o.w = sten(xc.z, xr,   xu.w, xd.w, xc.w);
    return o;
}

__device__ __forceinline__ float4 s4(float4 rv, float4 vv, float al) {
    float4 o;
    o.x = rv.x - al * vv.x;
    o.y = rv.y - al * vv.y;
    o.z = rv.z - al * vv.z;
    o.w = rv.w - al * vv.w;
    return o;
}
__device__ __forceinline__ float s1(int n, float al) {
    return __ldg(&g_r[n]) - al * __ldg(&g_v[n]);
}
__device__ __forceinline__ float sb1(const int* __restrict__ io,
                                     const float* __restrict__ bed,
                                     int r, int c, float al) {
    int n = r * C_ + c;
    float sv = s1(n, al);
    if (r == 0 || r == R_ - 1 || c == 0 || c == C_ - 1) {
        if (__ldg(&io[n]) == -1) sv = RWG_ * __ldg(&bed[n]);
    }
    return sv;
}
__device__ __forceinline__ float t_at(const int* __restrict__ io,
                                      const float* __restrict__ bed,
                                      int r, int c, float al) {
    float xc = sb1(io, bed, r, c, al);
    float a = 0.f;
    if (c > 0)      a += sb1(io, bed, r, c - 1, al) - xc;
    if (c < C_ - 1) a += sb1(io, bed, r, c + 1, al) - xc;
    if (r > 0)      a += sb1(io, bed, r - 1, c, al) - xc;
    if (r < R_ - 1) a += sb1(io, bed, r + 1, c, al) - xc;
    return a * INV_DX2_;
}

// ---------------- init helpers ----------------
__device__ __forceinline__ float xb0v(const int* __restrict__ io,
                                      const float* __restrict__ bed, int r, int c) {
    if (r == 0 || r == R_ - 1 || c == 0 || c == C_ - 1) {
        int n = r * C_ + c;
        if (__ldg(&io[n]) == -1) return RWG_ * __ldg(&bed[n]);
    }
    return 0.f;
}

__device__ __forceinline__ float init_r0_at(const int* __restrict__ io,
                                            const float* __restrict__ bed,
                                            int r, int c) {
    int n = r * C_ + c;
    float acc = 0.f;
    if (c < C_ - 1) acc += g_grad[r * (C_ - 1) + c];
    if (r < R_ - 1) acc += g_grad[HL_ + n];
    if (c > 0)      acc -= g_grad[r * (C_ - 1) + c - 1];
    if (r > 0)      acc -= g_grad[HL_ + n - C_];
    float b = acc * INV_DX_;
    float xc = xb0v(io, bed, r, c);
    float a = 0.f;
    if (c > 0)      a += xb0v(io, bed, r, c - 1) - xc;
    if (c < C_ - 1) a += xb0v(io, bed, r, c + 1) - xc;
    if (r > 0)      a += xb0v(io, bed, r - 1, c) - xc;
    if (r < R_ - 1) a += xb0v(io, bed, r + 1, c) - xc;
    return b - a * INV_DX2_;
}

// ---------------- prologue kernel: grad + zero slots + zero barriers --------
__global__ void __launch_bounds__(256) k_grad(const float* __restrict__ cs,
                                              const float* __restrict__ q,
                                              const int* __restrict__ fd) {
    int l = blockIdx.x * blockDim.x + threadIdx.x;
    if (blockIdx.x == 0) {
        for (int i = threadIdx.x; i < (ITERS_ + 2) * NSLOT; i += 256)
            g_rho[i] = (i == 0) ? 1.0 : 0.0;
        for (int i = threadIdx.x; i < (ITERS_ + 1) * NSLOT; i += 256) {
            double v = (i == 0) ? 1.0 : 0.0;
            g_dr0v[i] = v; g_dts[i] = v; g_dtt[i] = v;
        }
        for (int i = threadIdx.x; i < NPHASE; i += 256)
            ((unsigned*)g_bar)[i] = 0u;
    }
    if (l < L_) {
        float s = cs[l];
        float g = q[l] / (K_FLOW_ * powf(s, FLOW_EXP_));
        g_grad[l] = g * g * (float)fd[l];
    }
}

// ---------------- the persistent solver kernel ----------------
__global__ void __launch_bounds__(NTHR, 3) k_solve(const int* __restrict__ io,
                                                   const float* __restrict__ bed) {
    __shared__ float shs[2];
    const int gid  = blockIdx.x * NTHR + threadIdx.x;
    const int nt   = gridDim.x * NTHR;
    const int slot = blockIdx.x & (NSLOT - 1);
    int ph = 0;

    // ---- phase 0: r0 = b - A(0), zero x/p/v, rho[1] = dot(r0,r0) ----
    {
        float acc = 0.f;
        for (int i4 = gid; i4 < TOT4; i4 += nt) {
            int n = i4 << 2, rr = n >> 10, c0 = n & (C_ - 1);
            float4 r0v;
            r0v.x = init_r0_at(io, bed, rr, c0 + 0);
            r0v.y = init_r0_at(io, bed, rr, c0 + 1);
            r0v.z = init_r0_at(io, bed, rr, c0 + 2);
            r0v.w = init_r0_at(io, bed, rr, c0 + 3);
            ((float4*)g_r0)[i4] = r0v;
            ((float4*)g_r )[i4] = r0v;
            float4 z = make_float4(0.f, 0.f, 0.f, 0.f);
            ((float4*)g_x)[i4] = z;
            ((float4*)g_p)[i4] = z;
            ((float4*)g_v)[i4] = z;
            acc += dot4f(r0v, r0v);
        }
        red1f(acc, &g_rho[1 * NSLOT + slot]);
        gbar(ph++);
    }

    for (int it = 0; it < ITERS_; ++it) {
        // ---- phase 1: p = r + beta*(p - omega_prev*v) ----
        if (threadIdx.x == 0) {
            double rho_n   = slotsum(&g_rho [(it + 1) * NSLOT]);
            double rho_p   = slotsum(&g_rho [ it      * NSLOT]);
            double alpha_p = rho_p / (slotsum(&g_dr0v[it * NSLOT]) + EPSD);
            double omega_p = slotsum(&g_dts[it * NSLOT]) /
                             (slotsum(&g_dtt[it * NSLOT]) + EPSD);
            shs[0] = (float)((rho_n / (rho_p + EPSD)) * (alpha_p / (omega_p + EPSD)));
            shs[1] = (float)omega_p;
        }
        __syncthreads();
        {
            float beta = shs[0], om = shs[1];
            for (int i4 = gid; i4 < TOT4; i4 += nt) {
                float4 rv = ((const float4*)g_r)[i4];
                float4 pv = ((const float4*)g_p)[i4];
                float4 vv = ((const float4*)g_v)[i4];
                float4 o;
                o.x = rv.x + beta * (pv.x - om * vv.x);
                o.y = rv.y + beta * (pv.y - om * vv.y);
                o.z = rv.z + beta * (pv.z - om * vv.z);
                o.w = rv.w + beta * (pv.w - om * vv.w);
                ((float4*)g_p)[i4] = o;
            }
        }
        gbar(ph++);

        // ---- phase 2: v = A(p), dot(r0,v) ----
        {
            float acc = 0.f;
            for (int i4 = gid; i4 < TOT4; i4 += nt) {
                int n = i4 << 2, rr = n >> 10, c0 = n & (C_ - 1);
                float4 vout;
                if (rr >= 2 && rr <= R_ - 3 && c0 >= 4 && c0 <= C_ - 8) {
                    float4 xc = ((const float4*)g_p)[i4];
                    float4 xu = ((const float4*)g_p)[i4 - F4ROW];
                    float4 xd = ((const float4*)g_p)[i4 + F4ROW];
                    float xl = __ldg(&g_p[n - 1]);
                    float xr = __ldg(&g_p[n + 4]);
                    vout = sten4(xc, xu, xd, xl, xr);
                } else {
                    vout.x = matvec_at(g_p, io, bed, rr, c0 + 0);
                    vout.y = matvec_at(g_p, io, bed, rr, c0 + 1);
                    vout.z = matvec_at(g_p, io, bed, rr, c0 + 2);
                    vout.w = matvec_at(g_p, io, bed, rr, c0 + 3);
                }
                ((float4*)g_v)[i4] = vout;
                acc += dot4f(((const float4*)g_r0)[i4], vout);
            }
            red1f(acc, &g_dr0v[(it + 1) * NSLOT + slot]);
        }
        gbar(ph++);

        // ---- phase 3: s = r - al*v ; t = A(s) ; dot(t,s), dot(t,t) ----
        if (threadIdx.x == 0) {
            double rho_n = slotsum(&g_rho[(it + 1) * NSLOT]);
            shs[0] = (float)(rho_n / (slotsum(&g_dr0v[(it + 1) * NSLOT]) + EPSD));
        }
        __syncthreads();
        {
            float al = shs[0];
            float ats = 0.f, att = 0.f;
            for (int i4 = gid; i4 < TOT4; i4 += nt) {
                int n = i4 << 2, rr = n >> 10, c0 = n & (C_ - 1);
                float4 t0, sc;
                if (rr >= 2 && rr <= R_ - 3 && c0 >= 4 && c0 <= C_ - 8) {
                    float4 sm_ = s4(((const float4*)g_r)[i4 - F4ROW],
                                    ((const float4*)g_v)[i4 - F4ROW], al);
                    sc         = s4(((const float4*)g_r)[i4],
                                    ((const float4*)g_v)[i4], al);
                    float4 sd  = s4(((const float4*)g_r)[i4 + F4ROW],
                                    ((const float4*)g_v)[i4 + F4ROW], al);
                    float sl = s1(n - 1, al);
                    float sr = s1(n + 4, al);
                    t0 = sten4(sc, sm_, sd, sl, sr);
                } else {
                    sc.x = s1(n + 0, al); sc.y = s1(n + 1, al);
                    sc.z = s1(n + 2, al); sc.w = s1(n + 3, al);
                    t0.x = t_at(io, bed, rr, c0 + 0, al);
                    t0.y = t_at(io, bed, rr, c0 + 1, al);
                    t0.z = t_at(io, bed, rr, c0 + 2, al);
                    t0.w = t_at(io, bed, rr, c0 + 3, al);
                }
                ((float4*)g_s)[i4] = sc;
                ((float4*)g_t)[i4] = t0;
                ats += dot4f(t0, sc);
                att += dot4f(t0, t0);
            }
            red2f(ats, att,
                  &g_dts[(it + 1) * NSLOT + slot],
                  &g_dtt[(it + 1) * NSLOT + slot]);
        }
        gbar(ph++);

        // ---- phase 4: x += al*p + om*s ; r = s - om*t ; dot(r0, r_new) ----
        if (threadIdx.x == 0) {
            double rho_n = slotsum(&g_rho[(it + 1) * NSLOT]);
            shs[0] = (float)(rho_n / (slotsum(&g_dr0v[(it + 1) * NSLOT]) + EPSD));
            shs[1] = (float)(slotsum(&g_dts[(it + 1) * NSLOT]) /
                             (slotsum(&g_dtt[(it + 1) * NSLOT]) + EPSD));
        }
        __syncthreads();
        {
            float al = shs[0], om = shs[1];
            float d = 0.f;
            for (int i4 = gid; i4 < TOT4; i4 += nt) {
                float4 xv  = ((const float4*)g_x )[i4];
                float4 pv  = ((const float4*)g_p )[i4];
                float4 sv  = ((const float4*)g_s )[i4];
                float4 tv  = ((const float4*)g_t )[i4];
                float4 r0v = ((const float4*)g_r0)[i4];
                float4 xn, rn;
                xn.x = (xv.x + al * pv.x) + om * sv.x;  rn.x = sv.x - om * tv.x;
                xn.y = (xv.y + al * pv.y) + om * sv.y;  rn.y = sv.y - om * tv.y;
                xn.z = (xv.z + al * pv.z) + om * sv.z;  rn.z = sv.z - om * tv.z;
                xn.w = (xv.w + al * pv.w) + om * sv.w;  rn.w = sv.w - om * tv.w;
                ((float4*)g_x)[i4] = xn;
                ((float4*)g_r)[i4] = rn;
                d += dot4f(r0v, rn);
            }
            red1f(d, &g_rho[(it + 2) * NSLOT + slot]);
        }
        gbar(ph++);
    }
}

// ---------------- epilogue ----------------
__device__ __forceinline__ float eff_at(const float* __restrict__ bed,
                                        const float* __restrict__ ob, int n) {
    float pd = g_x[n] - RWG_ * __ldg(&bed[n]);
    float o  = __ldg(&ob[n]);
    float wp = fminf(fmaxf(pd, 0.f), o);
    return o - wp;
}

__global__ void __launch_bounds__(256) k_out(const float* __restrict__ cs,
                                             const float* __restrict__ q,
                                             const int* __restrict__ fd,
                                             const int* __restrict__ head,
                                             const int* __restrict__ tail,
                                             float* __restrict__ out,
                                             const int* __restrict__ dtp,
                                             const float* __restrict__ bed,
                                             const float* __restrict__ ob) {
    int l = blockIdx.x * blockDim.x + threadIdx.x;
    if (l >= L_) return;
    float dtf = (float)__ldg(dtp);
    int h = __ldg(&head[l]), t = __ldg(&tail[l]);
    float el = fmaxf(0.5f * (eff_at(bed, ob, h) + eff_at(bed, ob, t)), 1.0f);
    float s = cs[l];
    float melt = A_OPEN_ * q[l] * g_grad[l] * (float)fd[l];
    float closure = C_CLOSE_ * (el * el * el) * s;
    out[l] = fmaxf(s + (melt - closure) * dtf, 0.001f);
}

// ---------------- launch ----------------
extern "C" void kernel_launch(void* const* d_in, const int* in_sizes, int n_in,
                              void* d_out, int out_size) {
    const float* cs   = (const float*)d_in[0];
    const float* q    = (const float*)d_in[1];
    const float* bed  = (const float*)d_in[2];
    const float* ob   = (const float*)d_in[3];
    const int*   fd   = (const int*)  d_in[4];
    const int*   io   = (const int*)  d_in[5];
    const int*   head = (const int*)  d_in[6];
    const int*   tail = (const int*)  d_in[7];
    const int*   dtp  = (const int*)  d_in[8];
    float* out = (float*)d_out;

    const int TB = 256;
    const int GB_L = (L_ + TB - 1) / TB;   // 8184

    // Deadlock-proof persistent grid: numSMs * max co-resident blocks/SM.
    // (Deterministic; host query APIs only, no allocations, capture-legal.)
    int dev = 0;
    cudaGetDevice(&dev);
    int nsm = 0;
    cudaDeviceGetAttribute(&nsm, cudaDevAttrMultiProcessorCount, dev);
    int occ = 0;
    cudaOccupancyMaxActiveBlocksPerMultiprocessor(&occ, k_solve, NTHR, 0);
    if (nsm <= 0) nsm = 1;
    if (occ <= 0) occ = 1;
    long long nblk = (long long)nsm * occ;
    if (nblk > 1024) nblk = 1024;
    if (nblk < 1) nblk = 1;

    k_grad<<<GB_L, TB>>>(cs, q, fd);
    k_solve<<<(int)nblk, NTHR>>>(io, bed);
    k_out<<<GB_L, TB>>>(cs, q, fd, head, tail, out, dtp, bed, ob);
}

// round 7
// speedup vs baseline: 1.2395x; 1.1450x over previous
#include <cuda_runtime.h>

// ---------------- problem constants (raster grid 1024x1024) ----------------
#define R_  1024
#define C_  1024
#define N_  (R_ * C_)
#define HL_ (R_ * (C_ - 1))          // horizontal links = 1,047,552
#define L_  (HL_ + (R_ - 1) * C_)    // total links = 2,095,104
#define ITERS_ 15
#define NSLOT 32
#define F4ROW (C_ / 4)               // 256 float4 per row
#define TOT4  (N_ / 4)               // 262144 float4 total

#define K_FLOW_  0.0405f
#define FLOW_EXP_ 1.25f
#define A_OPEN_  1.3455e-09f
#define C_CLOSE_ 7.11e-24f
#define RWG_     9810.0f             // rho_w * g
#define INV_DX_  (1.0f / 100.0f)
#define INV_DX2_ (1.0f / (100.0f * 100.0f))

// ---------------- device scratch (static; no allocations) ----------------
__device__ __align__(16) float g_x [N_];
__device__ __align__(16) float g_r [N_];
__device__ __align__(16) float g_pA[N_];
__device__ __align__(16) float g_pB[N_];
__device__ __align__(16) float g_vA[N_];
__device__ __align__(16) float g_vB[N_];
__device__ __align__(16) float g_s [N_];
__device__ __align__(16) float g_t [N_];
__device__ __align__(16) float g_r0[N_];
__device__ __align__(16) float g_grad[L_];

// BiCGSTAB scalar state: 32 contention-spread slots per logical scalar.
__device__ double g_rho [(ITERS_ + 2) * NSLOT];
__device__ double g_dr0v[(ITERS_ + 1) * NSLOT];
__device__ double g_dts [(ITERS_ + 1) * NSLOT];
__device__ double g_dtt [(ITERS_ + 1) * NSLOT];

#define EPSD 1e-30

__device__ __forceinline__ double slotsum(const double* p) {
    double a = 0.0;
    #pragma unroll
    for (int i = 0; i < NSLOT; i++) a += p[i];
    return a;
}

// ---------------- reductions: f32 to warp level, f64 above ----------------
__device__ __forceinline__ void red1f(float v, double* dst) {
    #pragma unroll
    for (int o = 16; o > 0; o >>= 1) v += __shfl_down_sync(0xffffffffu, v, o);
    __shared__ double sm1[8];
    int lane = threadIdx.x & 31, w = threadIdx.x >> 5;
    if (lane == 0) sm1[w] = (double)v;
    __syncthreads();
    if (threadIdx.x < 8) {
        double d = sm1[threadIdx.x];
        #pragma unroll
        for (int o = 4; o > 0; o >>= 1) d += __shfl_down_sync(0xffu, d, o);
        if (threadIdx.x == 0) atomicAdd(dst, d);
    }
}

__device__ __forceinline__ void red2f(float a, float b, double* da, double* db) {
    #pragma unroll
    for (int o = 16; o > 0; o >>= 1) {
        a += __shfl_down_sync(0xffffffffu, a, o);
        b += __shfl_down_sync(0xffffffffu, b, o);
    }
    __shared__ double sma[8], smb[8];
    int lane = threadIdx.x & 31, w = threadIdx.x >> 5;
    if (lane == 0) { sma[w] = (double)a; smb[w] = (double)b; }
    __syncthreads();
    if (threadIdx.x < 8) {
        double da_ = sma[threadIdx.x];
        double db_ = smb[threadIdx.x];
        #pragma unroll
        for (int o = 4; o > 0; o >>= 1) {
            da_ += __shfl_down_sync(0xffu, da_, o);
            db_ += __shfl_down_sync(0xffu, db_, o);
        }
        if (threadIdx.x == 0) { atomicAdd(da, da_); atomicAdd(db, db_); }
    }
}

__device__ __forceinline__ float dot4f(float4 a, float4 b) {
    return a.x * b.x + a.y * b.y + a.z * b.z + a.w * b.w;
}

// interior 5-point stencil, add order: left, right, up, down
__device__ __forceinline__ float sten(float l, float rt, float u, float d, float c) {
    float a = (l - c);
    a += (rt - c);
    a += (u - c);
    a += (d - c);
    return a * INV_DX2_;
}
__device__ __forceinline__ float4 sten4(float4 xc, float4 xu, float4 xd, float xl, float xr) {
    float4 o;
    o.x = sten(xl,   xc.y, xu.x, xd.x, xc.x);
    o.y = sten(xc.x, xc.z, xu.y, xd.y, xc.y);
    o.z = sten(xc.y, xc.w, xu.z, xd.z, xc.z);
    o.w = sten(xc.z, xr,   xu.w, xd.w, xc.w);
    return o;
}

__device__ __forceinline__ bool is_border(int r, int c) {
    return (r == 0 || r == R_ - 1 || c == 0 || c == C_ - 1);
}

// ---------------- prologue kernel: grad (float4) + scalar-slot init --------
__global__ void __launch_bounds__(256) k_grad(const float4* __restrict__ cs,
                                              const float4* __restrict__ q,
                                              const int4* __restrict__ fd) {
    int i = blockIdx.x * blockDim.x + threadIdx.x;   // over L_/4
    if (blockIdx.x == 0) {
        for (int j = threadIdx.x; j < (ITERS_ + 2) * NSLOT; j += 256)
            g_rho[j] = (j == 0) ? 1.0 : 0.0;
        for (int j = threadIdx.x; j < (ITERS_ + 1) * NSLOT; j += 256) {
            double v = (j == 0) ? 1.0 : 0.0;
            g_dr0v[j] = v; g_dts[j] = v; g_dtt[j] = v;
        }
    }
    if (i < L_ / 4) {
        float4 s = cs[i];
        float4 qq = q[i];
        int4  f = fd[i];
        float4 o;
        float gx = qq.x / (K_FLOW_ * powf(s.x, FLOW_EXP_)); o.x = gx * gx * (float)f.x;
        float gy = qq.y / (K_FLOW_ * powf(s.y, FLOW_EXP_)); o.y = gy * gy * (float)f.y;
        float gz = qq.z / (K_FLOW_ * powf(s.z, FLOW_EXP_)); o.z = gz * gz * (float)f.z;
        float gw = qq.w / (K_FLOW_ * powf(s.w, FLOW_EXP_)); o.w = gw * gw * (float)f.w;
        ((float4*)g_grad)[i] = o;
    }
}

// ---------------- init: r0 = b - A(0); zero x, pA, vA ----------------
__device__ __forceinline__ float xb0v(const int* __restrict__ io,
                                      const float* __restrict__ bed, int r, int c) {
    if (is_border(r, c)) {
        int n = r * C_ + c;
        if (__ldg(&io[n]) == -1) return RWG_ * __ldg(&bed[n]);
    }
    return 0.f;
}

__device__ __forceinline__ float init_r0_at(const int* __restrict__ io,
                                            const float* __restrict__ bed,
                                            int r, int c) {
    int n = r * C_ + c;
    float acc = 0.f;
    if (c < C_ - 1) acc += g_grad[r * (C_ - 1) + c];
    if (r < R_ - 1) acc += g_grad[HL_ + n];
    if (c > 0)      acc -= g_grad[r * (C_ - 1) + c - 1];
    if (r > 0)      acc -= g_grad[HL_ + n - C_];
    float b = acc * INV_DX_;
    float xc = xb0v(io, bed, r, c);
    float a = 0.f;
    if (c > 0)      a += xb0v(io, bed, r, c - 1) - xc;
    if (c < C_ - 1) a += xb0v(io, bed, r, c + 1) - xc;
    if (r > 0)      a += xb0v(io, bed, r - 1, c) - xc;
    if (r < R_ - 1) a += xb0v(io, bed, r + 1, c) - xc;
    return b - a * INV_DX2_;
}

__global__ void __launch_bounds__(256) k_init(const int* __restrict__ io,
                                              const float* __restrict__ bed) {
    int i4 = blockIdx.x * blockDim.x + threadIdx.x;   // over TOT4
    int n = i4 << 2;
    int r = n >> 10, c0 = n & (C_ - 1);
    float4 r0v;
    r0v.x = init_r0_at(io, bed, r, c0 + 0);
    r0v.y = init_r0_at(io, bed, r, c0 + 1);
    r0v.z = init_r0_at(io, bed, r, c0 + 2);
    r0v.w = init_r0_at(io, bed, r, c0 + 3);
    ((float4*)g_r0)[i4] = r0v;
    ((float4*)g_r )[i4] = r0v;
    float4 z = make_float4(0.f, 0.f, 0.f, 0.f);
    ((float4*)g_x )[i4] = z;
    ((float4*)g_pA)[i4] = z;
    ((float4*)g_vA)[i4] = z;
    red1f(dot4f(r0v, r0v), &g_rho[1 * NSLOT + (blockIdx.x & (NSLOT - 1))]);
}

// ---------------- pass 1 (fused): p_new = r + beta*(p_old - om*v_old);
//                  v_new = A(p_new);  dot(r0, v_new) --------------------------
__device__ __forceinline__ float4 pn4(float4 rv, float4 pv, float4 vv,
                                      float beta, float om) {
    float4 o;
    o.x = rv.x + beta * (pv.x - om * vv.x);
    o.y = rv.y + beta * (pv.y - om * vv.y);
    o.z = rv.z + beta * (pv.z - om * vv.z);
    o.w = rv.w + beta * (pv.w - om * vv.w);
    return o;
}
__device__ __forceinline__ float pn1(const float* __restrict__ pOld,
                                     const float* __restrict__ vOld,
                                     int n, float beta, float om) {
    return __ldg(&g_r[n]) + beta * (__ldg(&pOld[n]) - om * __ldg(&vOld[n]));
}
__device__ __forceinline__ float pnb1(const float* __restrict__ pOld,
                                      const float* __restrict__ vOld,
                                      const int* __restrict__ io,
                                      const float* __restrict__ bed,
                                      int r, int c, float beta, float om) {
    int n = r * C_ + c;
    float pv = pn1(pOld, vOld, n, beta, om);
    if (is_border(r, c)) {
        if (__ldg(&io[n]) == -1) pv = RWG_ * __ldg(&bed[n]);
    }
    return pv;
}
__device__ __forceinline__ float v_at(const float* __restrict__ pOld,
                                      const float* __restrict__ vOld,
                                      const int* __restrict__ io,
                                      const float* __restrict__ bed,
                                      int r, int c, float beta, float om) {
    float xc = pnb1(pOld, vOld, io, bed, r, c, beta, om);
    float a = 0.f;
    if (c > 0)      a += pnb1(pOld, vOld, io, bed, r, c - 1, beta, om) - xc;
    if (c < C_ - 1) a += pnb1(pOld, vOld, io, bed, r, c + 1, beta, om) - xc;
    if (r > 0)      a += pnb1(pOld, vOld, io, bed, r - 1, c, beta, om) - xc;
    if (r < R_ - 1) a += pnb1(pOld, vOld, io, bed, r + 1, c, beta, om) - xc;
    return a * INV_DX2_;
}

__global__ void __launch_bounds__(256) k_pass1(const int* __restrict__ io,
                                               const float* __restrict__ bed,
                                               int it, int pp) {
    const float* __restrict__ pOld = pp ? g_pB : g_pA;
    const float* __restrict__ vOld = pp ? g_vB : g_vA;
    float* __restrict__ pNew = pp ? g_pA : g_pB;
    float* __restrict__ vNew = pp ? g_vA : g_vB;

    __shared__ float shs[2];
    if (threadIdx.x == 0) {
        double rho_n   = slotsum(&g_rho [(it + 1) * NSLOT]);
        double rho_p   = slotsum(&g_rho [ it      * NSLOT]);
        double alpha_p = rho_p / (slotsum(&g_dr0v[it * NSLOT]) + EPSD);
        double omega_p = slotsum(&g_dts[it * NSLOT]) /
                         (slotsum(&g_dtt[it * NSLOT]) + EPSD);
        shs[0] = (float)((rho_n / (rho_p + EPSD)) * (alpha_p / (omega_p + EPSD)));
        shs[1] = (float)omega_p;
    }
    __syncthreads();
    float beta = shs[0], om = shs[1];

    int i4 = blockIdx.x * blockDim.x + threadIdx.x;   // over TOT4
    int n = i4 << 2, rr = n >> 10, c0 = n & (C_ - 1);
    float4 pc, vout;
    if (rr >= 2 && rr <= R_ - 3 && c0 >= 4 && c0 <= C_ - 8) {
        float4 pu = pn4(((const float4*)g_r)[i4 - F4ROW],
                        ((const float4*)pOld)[i4 - F4ROW],
                        ((const float4*)vOld)[i4 - F4ROW], beta, om);
        pc        = pn4(((const float4*)g_r)[i4],
                        ((const float4*)pOld)[i4],
                        ((const float4*)vOld)[i4], beta, om);
        float4 pd = pn4(((const float4*)g_r)[i4 + F4ROW],
                        ((const float4*)pOld)[i4 + F4ROW],
                        ((const float4*)vOld)[i4 + F4ROW], beta, om);
        float pl = pn1(pOld, vOld, n - 1, beta, om);
        float pr = pn1(pOld, vOld, n + 4, beta, om);
        vout = sten4(pc, pu, pd, pl, pr);
    } else {
        pc.x = pn1(pOld, vOld, n + 0, beta, om);
        pc.y = pn1(pOld, vOld, n + 1, beta, om);
        pc.z = pn1(pOld, vOld, n + 2, beta, om);
        pc.w = pn1(pOld, vOld, n + 3, beta, om);
        vout.x = v_at(pOld, vOld, io, bed, rr, c0 + 0, beta, om);
        vout.y = v_at(pOld, vOld, io, bed, rr, c0 + 1, beta, om);
        vout.z = v_at(pOld, vOld, io, bed, rr, c0 + 2, beta, om);
        vout.w = v_at(pOld, vOld, io, bed, rr, c0 + 3, beta, om);
    }
    ((float4*)pNew)[i4] = pc;
    ((float4*)vNew)[i4] = vout;
    red1f(dot4f(((const float4*)g_r0)[i4], vout),
          &g_dr0v[(it + 1) * NSLOT + (blockIdx.x & (NSLOT - 1))]);
}

// ---------------- pass 2: s = r - al*v ; t = A(s) ; dot(t,s), dot(t,t) ------
__device__ __forceinline__ float4 s4(float4 rv, float4 vv, float al) {
    float4 o;
    o.x = rv.x - al * vv.x;
    o.y = rv.y - al * vv.y;
    o.z = rv.z - al * vv.z;
    o.w = rv.w - al * vv.w;
    return o;
}
__device__ __forceinline__ float s1(const float* __restrict__ v, int n, float al) {
    return __ldg(&g_r[n]) - al * __ldg(&v[n]);
}
__device__ __forceinline__ float sb1(const float* __restrict__ v,
                                     const int* __restrict__ io,
                                     const float* __restrict__ bed,
                                     int r, int c, float al) {
    int n = r * C_ + c;
    float sv = s1(v, n, al);
    if (is_border(r, c)) {
        if (__ldg(&io[n]) == -1) sv = RWG_ * __ldg(&bed[n]);
    }
    return sv;
}
__device__ __forceinline__ float t_at(const float* __restrict__ v,
                                      const int* __restrict__ io,
                                      const float* __restrict__ bed,
                                      int r, int c, float al) {
    float xc = sb1(v, io, bed, r, c, al);
    float a = 0.f;
    if (c > 0)      a += sb1(v, io, bed, r, c - 1, al) - xc;
    if (c < C_ - 1) a += sb1(v, io, bed, r, c + 1, al) - xc;
    if (r > 0)      a += sb1(v, io, bed, r - 1, c, al) - xc;
    if (r < R_ - 1) a += sb1(v, io, bed, r + 1, c, al) - xc;
    return a * INV_DX2_;
}

__global__ void __launch_bounds__(256) k_pass2(const int* __restrict__ io,
                                               const float* __restrict__ bed,
                                               int it, int pp) {
    const float* __restrict__ v = pp ? g_vA : g_vB;   // v_new of this iter
    __shared__ float shs[1];
    if (threadIdx.x == 0) {
        double rho_n = slotsum(&g_rho[(it + 1) * NSLOT]);
        shs[0] = (float)(rho_n / (slotsum(&g_dr0v[(it + 1) * NSLOT]) + EPSD));
    }
    __syncthreads();
    float al = shs[0];
    int i4 = blockIdx.x * blockDim.x + threadIdx.x;
    int n = i4 << 2, rr = n >> 10, c0 = n & (C_ - 1);
    float4 t0, sc;
    if (rr >= 2 && rr <= R_ - 3 && c0 >= 4 && c0 <= C_ - 8) {
        float4 sm_ = s4(((const float4*)g_r)[i4 - F4ROW], ((const float4*)v)[i4 - F4ROW], al);
        sc         = s4(((const float4*)g_r)[i4],         ((const float4*)v)[i4],         al);
        float4 sd  = s4(((const float4*)g_r)[i4 + F4ROW], ((const float4*)v)[i4 + F4ROW], al);
        float sl = s1(v, n - 1, al);
        float sr = s1(v, n + 4, al);
        t0 = sten4(sc, sm_, sd, sl, sr);
    } else {
        sc.x = s1(v, n + 0, al); sc.y = s1(v, n + 1, al);
        sc.z = s1(v, n + 2, al); sc.w = s1(v, n + 3, al);
        t0.x = t_at(v, io, bed, rr, c0 + 0, al);
        t0.y = t_at(v, io, bed, rr, c0 + 1, al);
        t0.z = t_at(v, io, bed, rr, c0 + 2, al);
        t0.w = t_at(v, io, bed, rr, c0 + 3, al);
    }
    ((float4*)g_s)[i4] = sc;
    ((float4*)g_t)[i4] = t0;
    int slot = blockIdx.x & (NSLOT - 1);
    red2f(dot4f(t0, sc), dot4f(t0, t0),
          &g_dts[(it + 1) * NSLOT + slot], &g_dtt[(it + 1) * NSLOT + slot]);
}

// ---------------- pass 3: x += al*p + om*s ; r = s - om*t ; dot(r0, r_new) --
__global__ void __launch_bounds__(256) k_pass3(int it, int pp) {
    const float* __restrict__ p = pp ? g_pA : g_pB;   // p_new of this iter
    __shared__ float shs[2];
    if (threadIdx.x == 0) {
        double rho_n = slotsum(&g_rho[(it + 1) * NSLOT]);
        shs[0] = (float)(rho_n / (slotsum(&g_dr0v[(it + 1) * NSLOT]) + EPSD));
        shs[1] = (float)(slotsum(&g_dts[(it + 1) * NSLOT]) /
                         (slotsum(&g_dtt[(it + 1) * NSLOT]) + EPSD));
    }
    __syncthreads();
    float al = shs[0], om = shs[1];
    int i4 = blockIdx.x * blockDim.x + threadIdx.x;
    float4 xv  = ((const float4*)g_x )[i4];
    float4 pv  = ((const float4*)p   )[i4];
    float4 sv  = ((const float4*)g_s )[i4];
    float4 tv  = ((const float4*)g_t )[i4];
    float4 r0v = ((const float4*)g_r0)[i4];
    float4 xn, rn;
    xn.x = (xv.x + al * pv.x) + om * sv.x;  rn.x = sv.x - om * tv.x;
    xn.y = (xv.y + al * pv.y) + om * sv.y;  rn.y = sv.y - om * tv.y;
    xn.z = (xv.z + al * pv.z) + om * sv.z;  rn.z = sv.z - om * tv.z;
    xn.w = (xv.w + al * pv.w) + om * sv.w;  rn.w = sv.w - om * tv.w;
    ((float4*)g_x)[i4] = xn;
    ((float4*)g_r)[i4] = rn;
    red1f(dot4f(r0v, rn), &g_rho[(it + 2) * NSLOT + (blockIdx.x & (NSLOT - 1))]);
}

// ---------------- epilogue: analytic raster topology, no head/tail loads ----
__device__ __forceinline__ float eff_at(const float* __restrict__ bed,
                                        const float* __restrict__ ob, int n) {
    float pd = g_x[n] - RWG_ * __ldg(&bed[n]);
    float o  = __ldg(&ob[n]);
    float wp = fminf(fmaxf(pd, 0.f), o);
    return o - wp;
}

__device__ __forceinline__ float out_at(int l, float cs, float q, float grad,
                                        float fdl, float dtf,
                                        const float* __restrict__ bed,
                                        const float* __restrict__ ob) {
    int tail, head;
    if (l < HL_) {                       // horizontal link
        int r = l / (C_ - 1);
        int c = l - r * (C_ - 1);
        tail = r * C_ + c;
        head = tail + 1;
    } else {                             // vertical link
        tail = l - HL_;
        head = tail + C_;
    }
    float el = fmaxf(0.5f * (eff_at(bed, ob, head) + eff_at(bed, ob, tail)), 1.0f);
    float melt = A_OPEN_ * q * grad * fdl;
    float closure = C_CLOSE_ * (el * el * el) * cs;
    return fmaxf(cs + (melt - closure) * dtf, 0.001f);
}

__global__ void __launch_bounds__(256) k_out(const float4* __restrict__ cs,
                                             const float4* __restrict__ q,
                                             const int4* __restrict__ fd,
                                             float4* __restrict__ out,
                                             const int* __restrict__ dtp,
                                             const float* __restrict__ bed,
                                             const float* __restrict__ ob) {
    int i = blockIdx.x * blockDim.x + threadIdx.x;   // over L_/4
    if (i >= L_ / 4) return;
    float dtf = (float)__ldg(dtp);
    float4 c4 = cs[i];
    float4 q4 = q[i];
    int4  f4 = fd[i];
    float4 g4 = ((const float4*)g_grad)[i];
    int l = i << 2;
    float4 o;
    o.x = out_at(l + 0, c4.x, q4.x, g4.x, (float)f4.x, dtf, bed, ob);
    o.y = out_at(l + 1, c4.y, q4.y, g4.y, (float)f4.y, dtf, bed, ob);
    o.z = out_at(l + 2, c4.z, q4.z, g4.z, (float)f4.z, dtf, bed, ob);
    o.w = out_at(l + 3, c4.w, q4.w, g4.w, (float)f4.w, dtf, bed, ob);
    out[i] = o;
}

// ---------------- launch ----------------
extern "C" void kernel_launch(void* const* d_in, const int* in_sizes, int n_in,
                              void* d_out, int out_size) {
    const float* cs   = (const float*)d_in[0];
    const float* q    = (const float*)d_in[1];
    const float* bed  = (const float*)d_in[2];
    const float* ob   = (const float*)d_in[3];
    const int*   fd   = (const int*)  d_in[4];
    const int*   io   = (const int*)  d_in[5];
    // d_in[6]=head, d_in[7]=tail unused (analytic raster topology)
    const int*   dtp  = (const int*)  d_in[8];
    float* out = (float*)d_out;

    const int TB = 256;
    const int GB_L4 = (L_ / 4 + TB - 1) / TB;  // 2046
    const int GB_4  = TOT4 / TB;               // 1024

    k_grad<<<GB_L4, TB>>>((const float4*)cs, (const float4*)q, (const int4*)fd);
    k_init<<<GB_4, TB>>>(io, bed);

    for (int it = 0; it < ITERS_; ++it) {
        int pp = it & 1;
        k_pass1<<<GB_4, TB>>>(io, bed, it, pp);
        k_pass2<<<GB_4, TB>>>(io, bed, it, pp);
        k_pass3<<<GB_4, TB>>>(it, pp);
    }

    k_out<<<GB_L4, TB>>>((const float4*)cs, (const float4*)q, (const int4*)fd,
                         (float4*)out, dtp, bed, ob);
}

// round 9
// speedup vs baseline: 1.2885x; 1.0395x over previous
#include <cuda_runtime.h>

// ---------------- problem constants (raster grid 1024x1024) ----------------
#define R_  1024
#define C_  1024
#define N_  (R_ * C_)
#define HL_ (R_ * (C_ - 1))          // horizontal links = 1,047,552
#define L_  (HL_ + (R_ - 1) * C_)    // total links = 2,095,104
#define ITERS_ 15
#define NSLOT 32
#define F4ROW (C_ / 4)               // 256 float4 per row
#define TOT4  (N_ / 4)               // 262144 float4 total

#define K_FLOW_  0.0405f
#define FLOW_EXP_ 1.25f
#define A_OPEN_  1.3455e-09f
#define C_CLOSE_ 7.11e-24f
#define RWG_     9810.0f             // rho_w * g
#define INV_DX_  (1.0f / 100.0f)
#define INV_DX2_ (1.0f / (100.0f * 100.0f))

// tile shape: 8 rows x 32 f4 (128 floats) per block; halo 1 cell each side
#define TS_SLOTS 340                 // 10 rows * 34 f4 haloed region
#define SROWS 10
#define SCOLS 136

// ---------------- device scratch (static; no allocations) ----------------
__device__ __align__(16) float g_x [N_];
__device__ __align__(16) float g_r [N_];
__device__ __align__(16) float g_pA[N_];
__device__ __align__(16) float g_pB[N_];
__device__ __align__(16) float g_vA[N_];
__device__ __align__(16) float g_vB[N_];
__device__ __align__(16) float g_s [N_];
__device__ __align__(16) float g_t [N_];
__device__ __align__(16) float g_r0[N_];
__device__ __align__(16) float g_grad[L_];

// BiCGSTAB scalar state: 32 contention-spread slots per logical scalar.
__device__ double g_rho [(ITERS_ + 2) * NSLOT];
__device__ double g_dr0v[(ITERS_ + 1) * NSLOT];
__device__ double g_dts [(ITERS_ + 1) * NSLOT];
__device__ double g_dtt [(ITERS_ + 1) * NSLOT];

#define EPSD 1e-30

__device__ __forceinline__ double slotsum(const double* p) {
    double a = 0.0;
    #pragma unroll
    for (int i = 0; i < NSLOT; i++) a += p[i];
    return a;
}

// ---------------- reductions: f32 to warp level, f64 above ----------------
__device__ __forceinline__ void red1f(float v, double* dst) {
    #pragma unroll
    for (int o = 16; o > 0; o >>= 1) v += __shfl_down_sync(0xffffffffu, v, o);
    __shared__ double sm1[8];
    int lane = threadIdx.x & 31, w = threadIdx.x >> 5;
    if (lane == 0) sm1[w] = (double)v;
    __syncthreads();
    if (threadIdx.x < 8) {
        double d = sm1[threadIdx.x];
        #pragma unroll
        for (int o = 4; o > 0; o >>= 1) d += __shfl_down_sync(0xffu, d, o);
        if (threadIdx.x == 0) atomicAdd(dst, d);
    }
}

__device__ __forceinline__ void red2f(float a, float b, double* da, double* db) {
    #pragma unroll
    for (int o = 16; o > 0; o >>= 1) {
        a += __shfl_down_sync(0xffffffffu, a, o);
        b += __shfl_down_sync(0xffffffffu, b, o);
    }
    __shared__ double sma[8], smb[8];
    int lane = threadIdx.x & 31, w = threadIdx.x >> 5;
    if (lane == 0) { sma[w] = (double)a; smb[w] = (double)b; }
    __syncthreads();
    if (threadIdx.x < 8) {
        double da_ = sma[threadIdx.x];
        double db_ = smb[threadIdx.x];
        #pragma unroll
        for (int o = 4; o > 0; o >>= 1) {
            da_ += __shfl_down_sync(0xffu, da_, o);
            db_ += __shfl_down_sync(0xffu, db_, o);
        }
        if (threadIdx.x == 0) { atomicAdd(da, da_); atomicAdd(db, db_); }
    }
}

__device__ __forceinline__ float dot4f(float4 a, float4 b) {
    return a.x * b.x + a.y * b.y + a.z * b.z + a.w * b.w;
}

__device__ __forceinline__ bool is_border(int r, int c) {
    return (r == 0 || r == R_ - 1 || c == 0 || c == C_ - 1);
}

// pointwise update formulas (identical expressions everywhere)
__device__ __forceinline__ float4 pn4(float4 rv, float4 pv, float4 vv,
                                      float beta, float om) {
    float4 o;
    o.x = rv.x + beta * (pv.x - om * vv.x);
    o.y = rv.y + beta * (pv.y - om * vv.y);
    o.z = rv.z + beta * (pv.z - om * vv.z);
    o.w = rv.w + beta * (pv.w - om * vv.w);
    return o;
}
__device__ __forceinline__ float4 sn4(float4 rv, float4 vv, float al) {
    float4 o;
    o.x = rv.x - al * vv.x;
    o.y = rv.y - al * vv.y;
    o.z = rv.z - al * vv.z;
    o.w = rv.w - al * vv.w;
    return o;
}

// ---------------- prologue kernel: grad (float4) + scalar-slot init --------
__global__ void __launch_bounds__(256) k_grad(const float4* __restrict__ cs,
                                              const float4* __restrict__ q,
                                              const int4* __restrict__ fd) {
    int i = blockIdx.x * blockDim.x + threadIdx.x;   // over L_/4
    if (blockIdx.x == 0) {
        for (int j = threadIdx.x; j < (ITERS_ + 2) * NSLOT; j += 256)
            g_rho[j] = (j == 0) ? 1.0 : 0.0;
        for (int j = threadIdx.x; j < (ITERS_ + 1) * NSLOT; j += 256) {
            double v = (j == 0) ? 1.0 : 0.0;
            g_dr0v[j] = v; g_dts[j] = v; g_dtt[j] = v;
        }
    }
    if (i < L_ / 4) {
        float4 s = cs[i];
        float4 qq = q[i];
        int4  f = fd[i];
        float4 o;
        float gx = qq.x / (K_FLOW_ * powf(s.x, FLOW_EXP_)); o.x = gx * gx * (float)f.x;
        float gy = qq.y / (K_FLOW_ * powf(s.y, FLOW_EXP_)); o.y = gy * gy * (float)f.y;
        float gz = qq.z / (K_FLOW_ * powf(s.z, FLOW_EXP_)); o.z = gz * gz * (float)f.z;
        float gw = qq.w / (K_FLOW_ * powf(s.w, FLOW_EXP_)); o.w = gw * gw * (float)f.w;
        ((float4*)g_grad)[i] = o;
    }
}

// ---------------- init: r0 = b - A(0); zero x, pA, vA ----------------
__device__ __forceinline__ float xb0v(const int* __restrict__ io,
                                      const float* __restrict__ bed, int r, int c) {
    if (is_border(r, c)) {
        int n = r * C_ + c;
        if (__ldg(&io[n]) == -1) return RWG_ * __ldg(&bed[n]);
    }
    return 0.f;
}

__device__ __forceinline__ float init_r0_at(const int* __restrict__ io,
                                            const float* __restrict__ bed,
                                            int r, int c) {
    int n = r * C_ + c;
    float acc = 0.f;
    if (c < C_ - 1) acc += g_grad[r * (C_ - 1) + c];
    if (r < R_ - 1) acc += g_grad[HL_ + n];
    if (c > 0)      acc -= g_grad[r * (C_ - 1) + c - 1];
    if (r > 0)      acc -= g_grad[HL_ + n - C_];
    float b = acc * INV_DX_;
    float xc = xb0v(io, bed, r, c);
    float a = 0.f;
    if (c > 0)      a += xb0v(io, bed, r, c - 1) - xc;
    if (c < C_ - 1) a += xb0v(io, bed, r, c + 1) - xc;
    if (r > 0)      a += xb0v(io, bed, r - 1, c) - xc;
    if (r < R_ - 1) a += xb0v(io, bed, r + 1, c) - xc;
    return b - a * INV_DX2_;
}

__global__ void __launch_bounds__(256) k_init(const int* __restrict__ io,
                                              const float* __restrict__ bed) {
    int i4 = blockIdx.x * blockDim.x + threadIdx.x;   // over TOT4
    int n = i4 << 2;
    int r = n >> 10, c0 = n & (C_ - 1);
    float4 r0v;
    r0v.x = init_r0_at(io, bed, r, c0 + 0);
    r0v.y = init_r0_at(io, bed, r, c0 + 1);
    r0v.z = init_r0_at(io, bed, r, c0 + 2);
    r0v.w = init_r0_at(io, bed, r, c0 + 3);
    ((float4*)g_r0)[i4] = r0v;
    ((float4*)g_r )[i4] = r0v;
    float4 z = make_float4(0.f, 0.f, 0.f, 0.f);
    ((float4*)g_x )[i4] = z;
    ((float4*)g_pA)[i4] = z;
    ((float4*)g_vA)[i4] = z;
    red1f(dot4f(r0v, r0v), &g_rho[1 * NSLOT + (blockIdx.x & (NSLOT - 1))]);
}

// ---------------- pass 1 (smem-tiled): p_new = r + beta*(p - om*v);
//                  v_new = A(xb(p_new)) from smem;  dot(r0, v_new) ----------
__global__ void __launch_bounds__(256, 6) k_pass1(const int* __restrict__ io,
                                                  const float* __restrict__ bed,
                                                  int it, int pp) {
    const float* __restrict__ pOld = pp ? g_pB : g_pA;
    const float* __restrict__ vOld = pp ? g_vB : g_vA;
    float* __restrict__ pNew = pp ? g_pA : g_pB;
    float* __restrict__ vNew = pp ? g_vA : g_vB;

    __shared__ float sP[SROWS][SCOLS];
    __shared__ float shs[2];
    if (threadIdx.x == 0) {
        double rho_n   = slotsum(&g_rho [(it + 1) * NSLOT]);
        double rho_p   = slotsum(&g_rho [ it      * NSLOT]);
        double alpha_p = rho_p / (slotsum(&g_dr0v[it * NSLOT]) + EPSD);
        double omega_p = slotsum(&g_dts[it * NSLOT]) /
                         (slotsum(&g_dtt[it * NSLOT]) + EPSD);
        shs[0] = (float)((rho_n / (rho_p + EPSD)) * (alpha_p / (omega_p + EPSD)));
        shs[1] = (float)omega_p;
    }
    __syncthreads();
    float beta = shs[0], om = shs[1];

    int b = blockIdx.x;
    int tx = b & 7, ty = b >> 3;
    int row0 = ty << 3, col4 = tx << 5;
    bool edge = (ty == 0) || (ty == 127) || (tx == 0) || (tx == 7);

    // fill smem with xb-substituted p_new over haloed region
    for (int slot = threadIdx.x; slot < TS_SLOTS; slot += 256) {
        int hr = slot / 34, hc = slot - hr * 34;
        int grow = row0 - 1 + hr;
        int g4c  = col4 - 1 + hc;
        if ((unsigned)grow > (unsigned)(R_ - 1) ||
            (unsigned)g4c  > (unsigned)(F4ROW - 1)) continue;
        int i4 = (grow << 8) + g4c;
        float4 rv = ((const float4*)g_r)[i4];
        float4 pv = ((const float4*)pOld)[i4];
        float4 vv = ((const float4*)vOld)[i4];
        float4 pn = pn4(rv, pv, vv, beta, om);
        float vals[4] = {pn.x, pn.y, pn.z, pn.w};
        if (edge) {
            int nb = (grow << 10) + (g4c << 2);
            #pragma unroll
            for (int j = 0; j < 4; j++) {
                int gc = (g4c << 2) + j;
                if (is_border(grow, gc) && __ldg(&io[nb + j]) == -1)
                    vals[j] = RWG_ * __ldg(&bed[nb + j]);
            }
        }
        int sc = hc << 2;
        sP[hr][sc + 0] = vals[0];
        sP[hr][sc + 1] = vals[1];
        sP[hr][sc + 2] = vals[2];
        sP[hr][sc + 3] = vals[3];
    }
    __syncthreads();

    // own f4 output
    int r_i = threadIdx.x >> 5, c_i = threadIdx.x & 31;
    int grow = row0 + r_i, g4c = col4 + c_i;
    int i4 = (grow << 8) + g4c;
    // raw p_new for storage (identical expression; L1-hot loads)
    {
        float4 rv = ((const float4*)g_r)[i4];
        float4 pv = ((const float4*)pOld)[i4];
        float4 vv = ((const float4*)vOld)[i4];
        ((float4*)pNew)[i4] = pn4(rv, pv, vv, beta, om);
    }
    int hr = r_i + 1, sc = (c_i + 1) << 2;
    int gc0 = g4c << 2;
    float4 vout;
    #pragma unroll
    for (int j = 0; j < 4; j++) {
        float xc = sP[hr][sc + j];
        float a = 0.f;
        int gc = gc0 + j;
        if (gc > 0)          a += sP[hr][sc + j - 1] - xc;
        if (gc < C_ - 1)     a += sP[hr][sc + j + 1] - xc;
        if (grow > 0)        a += sP[hr - 1][sc + j] - xc;
        if (grow < R_ - 1)   a += sP[hr + 1][sc + j] - xc;
        ((float*)&vout)[j] = a * INV_DX2_;
    }
    ((float4*)vNew)[i4] = vout;
    red1f(dot4f(((const float4*)g_r0)[i4], vout),
          &g_dr0v[(it + 1) * NSLOT + (blockIdx.x & (NSLOT - 1))]);
}

// ---------------- pass 2 (smem-tiled): s = r - al*v ; t = A(xb(s)) ;
//                  dot(t,s), dot(t,t) ---------------------------------------
__global__ void __launch_bounds__(256, 6) k_pass2(const int* __restrict__ io,
                                                  const float* __restrict__ bed,
                                                  int it, int pp) {
    const float* __restrict__ v = pp ? g_vA : g_vB;   // v_new of this iter

    __shared__ float sS[SROWS][SCOLS];
    __shared__ float shs[1];
    if (threadIdx.x == 0) {
        double rho_n = slotsum(&g_rho[(it + 1) * NSLOT]);
        shs[0] = (float)(rho_n / (slotsum(&g_dr0v[(it + 1) * NSLOT]) + EPSD));
    }
    __syncthreads();
    float al = shs[0];

    int b = blockIdx.x;
    int tx = b & 7, ty = b >> 3;
    int row0 = ty << 3, col4 = tx << 5;
    bool edge = (ty == 0) || (ty == 127) || (tx == 0) || (tx == 7);

    for (int slot = threadIdx.x; slot < TS_SLOTS; slot += 256) {
        int hr = slot / 34, hc = slot - hr * 34;
        int grow = row0 - 1 + hr;
        int g4c  = col4 - 1 + hc;
        if ((unsigned)grow > (unsigned)(R_ - 1) ||
            (unsigned)g4c  > (unsigned)(F4ROW - 1)) continue;
        int i4 = (grow << 8) + g4c;
        float4 rv = ((const float4*)g_r)[i4];
        float4 vv = ((const float4*)v)[i4];
        float4 sn = sn4(rv, vv, al);
        float vals[4] = {sn.x, sn.y, sn.z, sn.w};
        if (edge) {
            int nb = (grow << 10) + (g4c << 2);
            #pragma unroll
            for (int j = 0; j < 4; j++) {
                int gc = (g4c << 2) + j;
                if (is_border(grow, gc) && __ldg(&io[nb + j]) == -1)
                    vals[j] = RWG_ * __ldg(&bed[nb + j]);
            }
        }
        int sc = hc << 2;
        sS[hr][sc + 0] = vals[0];
        sS[hr][sc + 1] = vals[1];
        sS[hr][sc + 2] = vals[2];
        sS[hr][sc + 3] = vals[3];
    }
    __syncthreads();

    int r_i = threadIdx.x >> 5, c_i = threadIdx.x & 31;
    int grow = row0 + r_i, g4c = col4 + c_i;
    int i4 = (grow << 8) + g4c;
    // raw s for storage + dots (identical expression; L1-hot loads)
    float4 sc_raw;
    {
        float4 rv = ((const float4*)g_r)[i4];
        float4 vv = ((const float4*)v)[i4];
        sc_raw = sn4(rv, vv, al);
        ((float4*)g_s)[i4] = sc_raw;
    }
    int hr = r_i + 1, sc = (c_i + 1) << 2;
    int gc0 = g4c << 2;
    float4 t0;
    #pragma unroll
    for (int j = 0; j < 4; j++) {
        float xc = sS[hr][sc + j];
        float a = 0.f;
        int gc = gc0 + j;
        if (gc > 0)          a += sS[hr][sc + j - 1] - xc;
        if (gc < C_ - 1)     a += sS[hr][sc + j + 1] - xc;
        if (grow > 0)        a += sS[hr - 1][sc + j] - xc;
        if (grow < R_ - 1)   a += sS[hr + 1][sc + j] - xc;
        ((float*)&t0)[j] = a * INV_DX2_;
    }
    ((float4*)g_t)[i4] = t0;
    int slot = blockIdx.x & (NSLOT - 1);
    red2f(dot4f(t0, sc_raw), dot4f(t0, t0),
          &g_dts[(it + 1) * NSLOT + slot], &g_dtt[(it + 1) * NSLOT + slot]);
}

// ---------------- pass 3: x += al*p + om*s ; r = s - om*t ; dot(r0, r_new) --
__global__ void __launch_bounds__(256) k_pass3(int it, int pp) {
    const float* __restrict__ p = pp ? g_pA : g_pB;   // p_new of this iter
    __shared__ float shs[2];
    if (threadIdx.x == 0) {
        double rho_n = slotsum(&g_rho[(it + 1) * NSLOT]);
        shs[0] = (float)(rho_n / (slotsum(&g_dr0v[(it + 1) * NSLOT]) + EPSD));
        shs[1] = (float)(slotsum(&g_dts[(it + 1) * NSLOT]) /
                         (slotsum(&g_dtt[(it + 1) * NSLOT]) + EPSD));
    }
    __syncthreads();
    float al = shs[0], om = shs[1];
    int i4 = blockIdx.x * blockDim.x + threadIdx.x;
    float4 xv  = ((const float4*)g_x )[i4];
    float4 pv  = ((const float4*)p   )[i4];
    float4 sv  = ((const float4*)g_s )[i4];
    float4 tv  = ((const float4*)g_t )[i4];
    float4 r0v = ((const float4*)g_r0)[i4];
    float4 xn, rn;
    xn.x = (xv.x + al * pv.x) + om * sv.x;  rn.x = sv.x - om * tv.x;
    xn.y = (xv.y + al * pv.y) + om * sv.y;  rn.y = sv.y - om * tv.y;
    xn.z = (xv.z + al * pv.z) + om * sv.z;  rn.z = sv.z - om * tv.z;
    xn.w = (xv.w + al * pv.w) + om * sv.w;  rn.w = sv.w - om * tv.w;
    ((float4*)g_x)[i4] = xn;
    ((float4*)g_r)[i4] = rn;
    red1f(dot4f(r0v, rn), &g_rho[(it + 2) * NSLOT + (blockIdx.x & (NSLOT - 1))]);
}

// ---------------- epilogue: analytic raster topology, no head/tail loads ----
__device__ __forceinline__ float eff_at(const float* __restrict__ bed,
                                        const float* __restrict__ ob, int n) {
    float pd = g_x[n] - RWG_ * __ldg(&bed[n]);
    float o  = __ldg(&ob[n]);
    float wp = fminf(fmaxf(pd, 0.f), o);
    return o - wp;
}

__device__ __forceinline__ float out_at(int l, float cs, float q, float grad,
                                        float fdl, float dtf,
                                        const float* __restrict__ bed,
                                        const float* __restrict__ ob) {
    int tail, head;
    if (l < HL_) {                       // horizontal link
        int r = l / (C_ - 1);
        int c = l - r * (C_ - 1);
        tail = r * C_ + c;
        head = tail + 1;
    } else {                             // vertical link
        tail = l - HL_;
        head = tail + C_;
    }
    float el = fmaxf(0.5f * (eff_at(bed, ob, head) + eff_at(bed, ob, tail)), 1.0f);
    float melt = A_OPEN_ * q * grad * fdl;
    float closure = C_CLOSE_ * (el * el * el) * cs;
    return fmaxf(cs + (melt - closure) * dtf, 0.001f);
}

__global__ void __launch_bounds__(256) k_out(const float4* __restrict__ cs,
                                             const float4* __restrict__ q,
                                             const int4* __restrict__ fd,
                                             float4* __restrict__ out,
                                             const int* __restrict__ dtp,
                                             const float* __restrict__ bed,
                                             const float* __restrict__ ob) {
    int i = blockIdx.x * blockDim.x + threadIdx.x;   // over L_/4
    if (i >= L_ / 4) return;
    float dtf = (float)__ldg(dtp);
    float4 c4 = cs[i];
    float4 q4 = q[i];
    int4  f4 = fd[i];
    float4 g4 = ((const float4*)g_grad)[i];
    int l = i << 2;
    float4 o;
    o.x = out_at(l + 0, c4.x, q4.x, g4.x, (float)f4.x, dtf, bed, ob);
    o.y = out_at(l + 1, c4.y, q4.y, g4.y, (float)f4.y, dtf, bed, ob);
    o.z = out_at(l + 2, c4.z, q4.z, g4.z, (float)f4.z, dtf, bed, ob);
    o.w = out_at(l + 3, c4.w, q4.w, g4.w, (float)f4.w, dtf, bed, ob);
    out[i] = o;
}

// ---------------- launch ----------------
extern "C" void kernel_launch(void* const* d_in, const int* in_sizes, int n_in,
                              void* d_out, int out_size) {
    const float* cs   = (const float*)d_in[0];
    const float* q    = (const float*)d_in[1];
    const float* bed  = (const float*)d_in[2];
    const float* ob   = (const float*)d_in[3];
    const int*   fd   = (const int*)  d_in[4];
    const int*   io   = (const int*)  d_in[5];
    // d_in[6]=head, d_in[7]=tail unused (analytic raster topology)
    const int*   dtp  = (const int*)  d_in[8];
    float* out = (float*)d_out;

    const int TB = 256;
    const int GB_L4 = (L_ / 4 + TB - 1) / TB;  // 2046
    const int GB_4  = TOT4 / TB;               // 1024

    k_grad<<<GB_L4, TB>>>((const float4*)cs, (const float4*)q, (const int4*)fd);
    k_init<<<GB_4, TB>>>(io, bed);

    for (int it = 0; it < ITERS_; ++it) {
        int pp = it & 1;
        k_pass1<<<GB_4, TB>>>(io, bed, it, pp);
        k_pass2<<<GB_4, TB>>>(io, bed, it, pp);
        k_pass3<<<GB_4, TB>>>(it, pp);
    }

    k_out<<<GB_L4, TB>>>((const float4*)cs, (const float4*)q, (const int4*)fd,
                         (float4*)out, dtp, bed, ob);
}

// round 10
// speedup vs baseline: 1.6367x; 1.2702x over previous
#include <cuda_runtime.h>

// ---------------- problem constants (raster grid 1024x1024) ----------------
#define R_  1024
#define C_  1024
#define N_  (R_ * C_)
#define HL_ (R_ * (C_ - 1))          // horizontal links = 1,047,552
#define L_  (HL_ + (R_ - 1) * C_)    // total links = 2,095,104
#define ITERS_ 15
#define NSLOT 32
#define F4ROW (C_ / 4)               // 256 float4 per row
#define TOT4  (N_ / 4)               // 262144 float4 total

#define K_FLOW_  0.0405f
#define FLOW_EXP_ 1.25f
#define A_OPEN_  1.3455e-09f
#define C_CLOSE_ 7.11e-24f
#define RWG_     9810.0f             // rho_w * g
#define INV_DX_  (1.0f / 100.0f)
#define INV_DX2_ (1.0f / (100.0f * 100.0f))

// tile: 16 rows x 32 f4 (128 floats) per block; 512 blocks; halo 1 cell
#define SROWS 18
#define SCOLS 136
#define TSLOTS (18 * 34)             // 612 haloed f4 slots

// ---------------- device scratch (static; no allocations) ----------------
__device__ __align__(16) float g_x [N_];
__device__ __align__(16) float g_r [N_];
__device__ __align__(16) float g_pA[N_];
__device__ __align__(16) float g_pB[N_];
__device__ __align__(16) float g_vA[N_];
__device__ __align__(16) float g_vB[N_];
__device__ __align__(16) float g_s [N_];
__device__ __align__(16) float g_t [N_];
__device__ __align__(16) float g_r0[N_];
__device__ __align__(16) float g_grad[L_];

// scalar slots (32 contention-spread each)
__device__ double g_rho1[NSLOT];                    // rho[1] = dot(r0,r0)
__device__ double g_dr0v[(ITERS_ + 1) * NSLOT];     // [0]=1 ; [i+1]=dot(r0,v)
__device__ double g_dts [(ITERS_ + 1) * NSLOT];     // [0]=1 ; [i+1]=dot(t,s)
__device__ double g_dtt [(ITERS_ + 1) * NSLOT];     // [0]=1 ; [i+1]=dot(t,t)
__device__ double g_dr0s[(ITERS_ + 1) * NSLOT];     // [i+1]=dot(r0,s)
__device__ double g_dr0t[(ITERS_ + 1) * NSLOT];     // [i+1]=dot(r0,t)

#define EPSD 1e-30

__device__ __forceinline__ double slotsum(const double* p) {
    double a = 0.0;
    #pragma unroll
    for (int i = 0; i < NSLOT; i++) a += p[i];
    return a;
}

// rho[k] (the reference's dot(r0, r) at start of iteration k-1)
__device__ double rho_of(int k) {
    if (k <= 0) return 1.0;
    if (k == 1) return slotsum(g_rho1);
    double om = slotsum(&g_dts[(k - 1) * NSLOT]) /
                (slotsum(&g_dtt[(k - 1) * NSLOT]) + EPSD);
    return slotsum(&g_dr0s[(k - 1) * NSLOT]) - om * slotsum(&g_dr0t[(k - 1) * NSLOT]);
}

// ---------------- reductions: f32 to warp level, f64 above ----------------
__device__ __forceinline__ void red1f(float v, double* dst) {
    #pragma unroll
    for (int o = 16; o > 0; o >>= 1) v += __shfl_down_sync(0xffffffffu, v, o);
    __shared__ double sm1[8];
    int lane = threadIdx.x & 31, w = threadIdx.x >> 5;
    if (lane == 0) sm1[w] = (double)v;
    __syncthreads();
    if (threadIdx.x < 8) {
        double d = sm1[threadIdx.x];
        #pragma unroll
        for (int o = 4; o > 0; o >>= 1) d += __shfl_down_sync(0xffu, d, o);
        if (threadIdx.x == 0) atomicAdd(dst, d);
    }
}

__device__ __forceinline__ void red4f(float a, float b, float c, float d,
                                      double* da, double* db, double* dc, double* dd) {
    #pragma unroll
    for (int o = 16; o > 0; o >>= 1) {
        a += __shfl_down_sync(0xffffffffu, a, o);
        b += __shfl_down_sync(0xffffffffu, b, o);
        c += __shfl_down_sync(0xffffffffu, c, o);
        d += __shfl_down_sync(0xffffffffu, d, o);
    }
    __shared__ double sma[8], smb[8], smc[8], smd[8];
    int lane = threadIdx.x & 31, w = threadIdx.x >> 5;
    if (lane == 0) { sma[w] = (double)a; smb[w] = (double)b;
                     smc[w] = (double)c; smd[w] = (double)d; }
    __syncthreads();
    if (threadIdx.x < 8) {
        double a_ = sma[threadIdx.x], b_ = smb[threadIdx.x];
        double c_ = smc[threadIdx.x], d_ = smd[threadIdx.x];
        #pragma unroll
        for (int o = 4; o > 0; o >>= 1) {
            a_ += __shfl_down_sync(0xffu, a_, o);
            b_ += __shfl_down_sync(0xffu, b_, o);
            c_ += __shfl_down_sync(0xffu, c_, o);
            d_ += __shfl_down_sync(0xffu, d_, o);
        }
        if (threadIdx.x == 0) {
            atomicAdd(da, a_); atomicAdd(db, b_);
            atomicAdd(dc, c_); atomicAdd(dd, d_);
        }
    }
}

__device__ __forceinline__ float dot4f(float4 a, float4 b) {
    return a.x * b.x + a.y * b.y + a.z * b.z + a.w * b.w;
}

__device__ __forceinline__ bool is_border(int r, int c) {
    return (r == 0 || r == R_ - 1 || c == 0 || c == C_ - 1);
}

// ---------------- prologue kernel: grad (float4) + scalar-slot init --------
__global__ void __launch_bounds__(256) k_grad(const float4* __restrict__ cs,
                                              const float4* __restrict__ q,
                                              const int4* __restrict__ fd) {
    int i = blockIdx.x * blockDim.x + threadIdx.x;   // over L_/4
    if (blockIdx.x == 0) {
        for (int j = threadIdx.x; j < NSLOT; j += 256) g_rho1[j] = 0.0;
        for (int j = threadIdx.x; j < (ITERS_ + 1) * NSLOT; j += 256) {
            double v = (j == 0) ? 1.0 : 0.0;
            g_dr0v[j] = v; g_dts[j] = v; g_dtt[j] = v;
            g_dr0s[j] = 0.0; g_dr0t[j] = 0.0;
        }
    }
    if (i < L_ / 4) {
        float4 s = cs[i];
        float4 qq = q[i];
        int4  f = fd[i];
        float4 o;
        float gx = qq.x / (K_FLOW_ * powf(s.x, FLOW_EXP_)); o.x = gx * gx * (float)f.x;
        float gy = qq.y / (K_FLOW_ * powf(s.y, FLOW_EXP_)); o.y = gy * gy * (float)f.y;
        float gz = qq.z / (K_FLOW_ * powf(s.z, FLOW_EXP_)); o.z = gz * gz * (float)f.z;
        float gw = qq.w / (K_FLOW_ * powf(s.w, FLOW_EXP_)); o.w = gw * gw * (float)f.w;
        ((float4*)g_grad)[i] = o;
    }
}

// ---------------- init: r0 = b - A(0); zero x, pA, vA ----------------
__device__ __forceinline__ float xb0v(const int* __restrict__ io,
                                      const float* __restrict__ bed, int r, int c) {
    if (is_border(r, c)) {
        int n = r * C_ + c;
        if (__ldg(&io[n]) == -1) return RWG_ * __ldg(&bed[n]);
    }
    return 0.f;
}

__device__ __forceinline__ float init_r0_at(const int* __restrict__ io,
                                            const float* __restrict__ bed,
                                            int r, int c) {
    int n = r * C_ + c;
    float acc = 0.f;
    if (c < C_ - 1) acc += g_grad[r * (C_ - 1) + c];
    if (r < R_ - 1) acc += g_grad[HL_ + n];
    if (c > 0)      acc -= g_grad[r * (C_ - 1) + c - 1];
    if (r > 0)      acc -= g_grad[HL_ + n - C_];
    float b = acc * INV_DX_;
    float xc = xb0v(io, bed, r, c);
    float a = 0.f;
    if (c > 0)      a += xb0v(io, bed, r, c - 1) - xc;
    if (c < C_ - 1) a += xb0v(io, bed, r, c + 1) - xc;
    if (r > 0)      a += xb0v(io, bed, r - 1, c) - xc;
    if (r < R_ - 1) a += xb0v(io, bed, r + 1, c) - xc;
    return b - a * INV_DX2_;
}

__global__ void __launch_bounds__(256) k_init(const int* __restrict__ io,
                                              const float* __restrict__ bed) {
    int i4 = blockIdx.x * blockDim.x + threadIdx.x;   // over TOT4
    int n = i4 << 2;
    int r = n >> 10, c0 = n & (C_ - 1);
    float4 r0v;
    r0v.x = init_r0_at(io, bed, r, c0 + 0);
    r0v.y = init_r0_at(io, bed, r, c0 + 1);
    r0v.z = init_r0_at(io, bed, r, c0 + 2);
    r0v.w = init_r0_at(io, bed, r, c0 + 3);
    ((float4*)g_r0)[i4] = r0v;
    ((float4*)g_r )[i4] = r0v;
    float4 z = make_float4(0.f, 0.f, 0.f, 0.f);
    ((float4*)g_x )[i4] = z;
    ((float4*)g_pA)[i4] = z;
    ((float4*)g_vA)[i4] = z;
    red1f(dot4f(r0v, r0v), &g_rho1[blockIdx.x & (NSLOT - 1)]);
}

// ---------------- K_A: r_cur = s - om_p*t (it>=1) ; x += al_p*p + om_p*s ;
//    p_new = r_cur + beta*(p_old - om_p*v_old) ; v_new = A(xb(p_new)) ;
//    dot(r0, v_new) --------------------------------------------------------
__global__ void __launch_bounds__(256, 4) k_A(const int* __restrict__ io,
                                              const float* __restrict__ bed,
                                              int it) {
    int pp = it & 1;
    const float* __restrict__ pOld = pp ? g_pB : g_pA;
    const float* __restrict__ vOld = pp ? g_vB : g_vA;
    float* __restrict__ pNew = pp ? g_pA : g_pB;
    float* __restrict__ vNew = pp ? g_vA : g_vB;
    const bool first = (it == 0);

    __shared__ float sP[SROWS][SCOLS];
    __shared__ float shs[3];
    if (threadIdx.x == 0) {
        double om_p  = slotsum(&g_dts[it * NSLOT]) /
                       (slotsum(&g_dtt[it * NSLOT]) + EPSD);
        double rho_p = rho_of(it);
        double al_p  = rho_p / (slotsum(&g_dr0v[it * NSLOT]) + EPSD);
        double rho_n = rho_of(it + 1);
        shs[0] = (float)((rho_n / (rho_p + EPSD)) * (al_p / (om_p + EPSD)));  // beta
        shs[1] = (float)om_p;
        shs[2] = (float)al_p;
    }
    __syncthreads();
    float beta = shs[0], om = shs[1], al = shs[2];

    int b = blockIdx.x;                  // 512 blocks: 64 tile-rows x 8 tile-cols
    int tx = b & 7, ty = b >> 3;
    int row0 = ty << 4, col4 = tx << 5;
    bool edge = (ty == 0) || (ty == 63) || (tx == 0) || (tx == 7);

    // fill smem with xb-substituted p_new over haloed region
    for (int slot = threadIdx.x; slot < TSLOTS; slot += 256) {
        int hr = slot / 34, hc = slot - hr * 34;
        int grow = row0 - 1 + hr;
        int g4c  = col4 - 1 + hc;
        if ((unsigned)grow > (unsigned)(R_ - 1) ||
            (unsigned)g4c  > (unsigned)(F4ROW - 1)) continue;
        int i4 = (grow << 8) + g4c;
        float4 pv = ((const float4*)pOld)[i4];
        float4 vv = ((const float4*)vOld)[i4];
        float4 rn;
        if (first) {
            rn = ((const float4*)g_r)[i4];
        } else {
            float4 sv = ((const float4*)g_s)[i4];
            float4 tv = ((const float4*)g_t)[i4];
            rn.x = sv.x - om * tv.x;  rn.y = sv.y - om * tv.y;
            rn.z = sv.z - om * tv.z;  rn.w = sv.w - om * tv.w;
        }
        float vals[4];
        vals[0] = rn.x + beta * (pv.x - om * vv.x);
        vals[1] = rn.y + beta * (pv.y - om * vv.y);
        vals[2] = rn.z + beta * (pv.z - om * vv.z);
        vals[3] = rn.w + beta * (pv.w - om * vv.w);
        if (edge) {
            int nb = (grow << 10) + (g4c << 2);
            #pragma unroll
            for (int j = 0; j < 4; j++) {
                int gc = (g4c << 2) + j;
                if (is_border(grow, gc) && __ldg(&io[nb + j]) == -1)
                    vals[j] = RWG_ * __ldg(&bed[nb + j]);
            }
        }
        int sc = hc << 2;
        sP[hr][sc + 0] = vals[0];
        sP[hr][sc + 1] = vals[1];
        sP[hr][sc + 2] = vals[2];
        sP[hr][sc + 3] = vals[3];
    }
    __syncthreads();

    // two output rows per thread: r_i and r_i + 8
    int r_i = threadIdx.x >> 5, c_i = threadIdx.x & 31;
    int g4c = col4 + c_i;
    int gc0 = g4c << 2;
    float acc = 0.f;
    #pragma unroll
    for (int k = 0; k < 2; k++) {
        int grow = row0 + r_i + (k << 3);
        int i4 = (grow << 8) + g4c;
        float4 pv = ((const float4*)pOld)[i4];
        float4 vv = ((const float4*)vOld)[i4];
        float4 rn;
        if (first) {
            rn = ((const float4*)g_r)[i4];
        } else {
            float4 sv = ((const float4*)g_s)[i4];
            float4 tv = ((const float4*)g_t)[i4];
            rn.x = sv.x - om * tv.x;  rn.y = sv.y - om * tv.y;
            rn.z = sv.z - om * tv.z;  rn.w = sv.w - om * tv.w;
            ((float4*)g_r)[i4] = rn;
            // deferred x update of iteration it-1 (identical expression)
            float4 xv = ((const float4*)g_x)[i4];
            float4 xn;
            xn.x = (xv.x + al * pv.x) + om * sv.x;
            xn.y = (xv.y + al * pv.y) + om * sv.y;
            xn.z = (xv.z + al * pv.z) + om * sv.z;
            xn.w = (xv.w + al * pv.w) + om * sv.w;
            ((float4*)g_x)[i4] = xn;
        }
        float4 pn;
        pn.x = rn.x + beta * (pv.x - om * vv.x);
        pn.y = rn.y + beta * (pv.y - om * vv.y);
        pn.z = rn.z + beta * (pv.z - om * vv.z);
        pn.w = rn.w + beta * (pv.w - om * vv.w);
        ((float4*)pNew)[i4] = pn;

        int hr = r_i + 1 + (k << 3), sc = (c_i + 1) << 2;
        float4 vout;
        #pragma unroll
        for (int j = 0; j < 4; j++) {
            float xc = sP[hr][sc + j];
            float a = 0.f;
            int gc = gc0 + j;
            if (gc > 0)          a += sP[hr][sc + j - 1] - xc;
            if (gc < C_ - 1)     a += sP[hr][sc + j + 1] - xc;
            if (grow > 0)        a += sP[hr - 1][sc + j] - xc;
            if (grow < R_ - 1)   a += sP[hr + 1][sc + j] - xc;
            ((float*)&vout)[j] = a * INV_DX2_;
        }
        ((float4*)vNew)[i4] = vout;
        acc += dot4f(((const float4*)g_r0)[i4], vout);
    }
    red1f(acc, &g_dr0v[(it + 1) * NSLOT + (blockIdx.x & (NSLOT - 1))]);
}

// ---------------- K_B: s = r - al*v ; t = A(xb(s)) ;
//    dots (t,s),(t,t),(r0,s),(r0,t) -----------------------------------------
__global__ void __launch_bounds__(256, 4) k_B(const int* __restrict__ io,
                                              const float* __restrict__ bed,
                                              int it) {
    int pp = it & 1;
    const float* __restrict__ v = pp ? g_vA : g_vB;   // v_new of this iter

    __shared__ float sS[SROWS][SCOLS];
    __shared__ float shs[1];
    if (threadIdx.x == 0) {
        double rho_n = rho_of(it + 1);
        shs[0] = (float)(rho_n / (slotsum(&g_dr0v[(it + 1) * NSLOT]) + EPSD));
    }
    __syncthreads();
    float al = shs[0];

    int b = blockIdx.x;
    int tx = b & 7, ty = b >> 3;
    int row0 = ty << 4, col4 = tx << 5;
    bool edge = (ty == 0) || (ty == 63) || (tx == 0) || (tx == 7);

    for (int slot = threadIdx.x; slot < TSLOTS; slot += 256) {
        int hr = slot / 34, hc = slot - hr * 34;
        int grow = row0 - 1 + hr;
        int g4c  = col4 - 1 + hc;
        if ((unsigned)grow > (unsigned)(R_ - 1) ||
            (unsigned)g4c  > (unsigned)(F4ROW - 1)) continue;
        int i4 = (grow << 8) + g4c;
        float4 rv = ((const float4*)g_r)[i4];
        float4 vv = ((const float4*)v)[i4];
        float vals[4];
        vals[0] = rv.x - al * vv.x;
        vals[1] = rv.y - al * vv.y;
        vals[2] = rv.z - al * vv.z;
        vals[3] = rv.w - al * vv.w;
        if (edge) {
            int nb = (grow << 10) + (g4c << 2);
            #pragma unroll
            for (int j = 0; j < 4; j++) {
                int gc = (g4c << 2) + j;
                if (is_border(grow, gc) && __ldg(&io[nb + j]) == -1)
                    vals[j] = RWG_ * __ldg(&bed[nb + j]);
            }
        }
        int sc = hc << 2;
        sS[hr][sc + 0] = vals[0];
        sS[hr][sc + 1] = vals[1];
        sS[hr][sc + 2] = vals[2];
        sS[hr][sc + 3] = vals[3];
    }
    __syncthreads();

    int r_i = threadIdx.x >> 5, c_i = threadIdx.x & 31;
    int g4c = col4 + c_i;
    int gc0 = g4c << 2;
    float ats = 0.f, att = 0.f, ar0s = 0.f, ar0t = 0.f;
    #pragma unroll
    for (int k = 0; k < 2; k++) {
        int grow = row0 + r_i + (k << 3);
        int i4 = (grow << 8) + g4c;
        float4 rv = ((const float4*)g_r)[i4];
        float4 vv = ((const float4*)v)[i4];
        float4 sc_raw;
        sc_raw.x = rv.x - al * vv.x;
        sc_raw.y = rv.y - al * vv.y;
        sc_raw.z = rv.z - al * vv.z;
        sc_raw.w = rv.w - al * vv.w;
        ((float4*)g_s)[i4] = sc_raw;

        int hr = r_i + 1 + (k << 3), sc = (c_i + 1) << 2;
        float4 t0;
        #pragma unroll
        for (int j = 0; j < 4; j++) {
            float xc = sS[hr][sc + j];
            float a = 0.f;
            int gc = gc0 + j;
            if (gc > 0)          a += sS[hr][sc + j - 1] - xc;
            if (gc < C_ - 1)     a += sS[hr][sc + j + 1] - xc;
            if (grow > 0)        a += sS[hr - 1][sc + j] - xc;
            if (grow < R_ - 1)   a += sS[hr + 1][sc + j] - xc;
            ((float*)&t0)[j] = a * INV_DX2_;
        }
        ((float4*)g_t)[i4] = t0;
        float4 r0v = ((const float4*)g_r0)[i4];
        ats  += dot4f(t0, sc_raw);
        att  += dot4f(t0, t0);
        ar0s += dot4f(r0v, sc_raw);
        ar0t += dot4f(r0v, t0);
    }
    int slot = (it + 1) * NSLOT + (blockIdx.x & (NSLOT - 1));
    red4f(ats, att, ar0s, ar0t,
          &g_dts[slot], &g_dtt[slot], &g_dr0s[slot], &g_dr0t[slot]);
}

// ---------------- epilogue: analytic topology + final x on the fly ----------
__global__ void __launch_bounds__(256) k_out(const float4* __restrict__ cs,
                                             const float4* __restrict__ q,
                                             const int4* __restrict__ fd,
                                             float4* __restrict__ out,
                                             const int* __restrict__ dtp,
                                             const float* __restrict__ bed,
                                             const float* __restrict__ ob) {
    __shared__ float shs[2];
    if (threadIdx.x == 0) {
        // scalars of final iteration (it = ITERS_-1 = 14)
        double rho_n = rho_of(ITERS_);
        shs[0] = (float)(rho_n / (slotsum(&g_dr0v[ITERS_ * NSLOT]) + EPSD));  // al14
        shs[1] = (float)(slotsum(&g_dts[ITERS_ * NSLOT]) /
                         (slotsum(&g_dtt[ITERS_ * NSLOT]) + EPSD));           // om14
    }
    __syncthreads();
    float al = shs[0], om = shs[1];

    int i = blockIdx.x * blockDim.x + threadIdx.x;   // over L_/4
    if (i >= L_ / 4) return;
    float dtf = (float)__ldg(dtp);
    float4 c4 = cs[i];
    float4 q4 = q[i];
    int4  f4 = fd[i];
    float4 g4 = ((const float4*)g_grad)[i];
    int l0 = i << 2;
    float4 o;
    #pragma unroll
    for (int j = 0; j < 4; j++) {
        int l = l0 + j;
        int tail, head;
        if (l < HL_) {
            int r = l / (C_ - 1);
            int c = l - r * (C_ - 1);
            tail = r * C_ + c;
            head = tail + 1;
        } else {
            tail = l - HL_;
            head = tail + C_;
        }
        // eff at head/tail with final-x computed on the fly (identical exprs)
        float effs[2];
        int nn[2] = {head, tail};
        #pragma unroll
        for (int m = 0; m < 2; m++) {
            int n = nn[m];
            // final p buffer is g_pB (pNew of it=14, pp=0)
            float xf = (__ldg(&g_x[n]) + al * __ldg(&g_pB[n])) + om * __ldg(&g_s[n]);
            float pd = xf - RWG_ * __ldg(&bed[n]);
            float ov = __ldg(&ob[n]);
            float wp = fminf(fmaxf(pd, 0.f), ov);
            effs[m] = ov - wp;
        }
        float el = fmaxf(0.5f * (effs[0] + effs[1]), 1.0f);
        float csv = ((const float*)&c4)[j];
        float melt = A_OPEN_ * ((const float*)&q4)[j] * ((const float*)&g4)[j]
                   * (float)((const int*)&f4)[j];
        float closure = C_CLOSE_ * (el * el * el) * csv;
        ((float*)&o)[j] = fmaxf(csv + (melt - closure) * dtf, 0.001f);
    }
    out[i] = o;
}

// ---------------- launch ----------------
extern "C" void kernel_launch(void* const* d_in, const int* in_sizes, int n_in,
                              void* d_out, int out_size) {
    const float* cs   = (const float*)d_in[0];
    const float* q    = (const float*)d_in[1];
    const float* bed  = (const float*)d_in[2];
    const float* ob   = (const float*)d_in[3];
    const int*   fd   = (const int*)  d_in[4];
    const int*   io   = (const int*)  d_in[5];
    // d_in[6]=head, d_in[7]=tail unused (analytic raster topology)
    const int*   dtp  = (const int*)  d_in[8];
    float* out = (float*)d_out;

    const int TB = 256;
    const int GB_L4 = (L_ / 4 + TB - 1) / TB;  // 2046
    const int GB_4  = TOT4 / TB;               // 1024
    const int GB_T  = 512;                     // 64 x 8 tiles (single wave)

    k_grad<<<GB_L4, TB>>>((const float4*)cs, (const float4*)q, (const int4*)fd);
    k_init<<<GB_4, TB>>>(io, bed);

    for (int it = 0; it < ITERS_; ++it) {
        k_A<<<GB_T, TB>>>(io, bed, it);
        k_B<<<GB_T, TB>>>(io, bed, it);
    }

    k_out<<<GB_L4, TB>>>((const float4*)cs, (const float4*)q, (const int4*)fd,
                         (float4*)out, dtp, bed, ob);
}